// round 1
// baseline (speedup 1.0000x reference)
#include <cuda_runtime.h>
#include <math.h>

#define BB 8
#define LL 2048
#define DD 512
#define MM 8
#define DHH 64
#define KHH 256

// ---------------- scratch (device globals; no allocations) ----------------
__device__ float g_W1[64 * 2048 * 256];      // [bm][l][kh] 128MB
__device__ float g_W2[64 * 2048 * 256];      // [bm][l][kh] 128MB
__device__ float g_S[64 * 64 * 256];         // [bm][d][kh] 4MB
__device__ float g_mixpre[BB * LL * DD];
__device__ float g_mix[BB * LL * DD];
__device__ float g_u[BB * LL * DD];
__device__ float g_c0[BB * LL * DD];
__device__ float g_v[BB * LL * DD];
__device__ float g_w[BB * LL * DD];

__device__ __forceinline__ float geluf(float x) {
    return 0.5f * x * (1.0f + erff(x * 0.7071067811865476f));
}
__device__ __forceinline__ float sigmoidf_(float x) {
    return 1.0f / (1.0f + expf(-x));
}
__device__ __forceinline__ float pe_val(int l, int c) {
    float ang = (float)l * expf(-(float)(c & ~1) * 0.0179889460390160f);
    return (c & 1) ? cosf(ang) : sinf(ang);
}

// ---------------- kernel 1: hyper MLPs (W1 / W2 generation) ----------------
// grid (L/32, B*M, 2); 256 threads; dynamic smem
__global__ void __launch_bounds__(256)
pmlp_kernel(const float* __restrict__ x,
            const float* __restrict__ f1w_1, const float* __restrict__ f1b_1,
            const float* __restrict__ f2w_1, const float* __restrict__ f2b_1,
            const float* __restrict__ f1w_2, const float* __restrict__ f1b_2,
            const float* __restrict__ f2w_2, const float* __restrict__ f2b_2)
{
    extern __shared__ float sm[];
    float* fc1s = sm;                  // [f][h] pitch 65 : 64*65
    float* fc2s = fc1s + 64 * 65;      // [h][o] pitch 257: 64*257
    float* b1s  = fc2s + 64 * 257;     // 64
    float* b2s  = b1s + 64;            // 256
    float* xs   = b2s + 256;           // [tok][f] pitch 65: 32*65
    float* hs   = xs + 32 * 65;        // [tok][h] pitch 65: 32*65

    int tid = threadIdx.x;
    int l0 = blockIdx.x * 32;
    int bm = blockIdx.y;
    int b = bm >> 3, m = bm & 7;
    int which = blockIdx.z;
    const float* f1w = which ? f1w_2 : f1w_1;
    const float* f1b = which ? f1b_2 : f1b_1;
    const float* f2w = which ? f2w_2 : f2w_1;
    const float* f2b = which ? f2b_2 : f2b_1;
    float* Wout = which ? g_W2 : g_W1;

    for (int i = tid; i < 64 * 64; i += 256) {
        int h = i >> 6, f = i & 63;
        fc1s[f * 65 + h] = f1w[m * 4096 + i];
    }
    for (int i = tid; i < 256 * 64; i += 256) {
        int o = i >> 6, h = i & 63;
        fc2s[h * 257 + o] = f2w[m * 16384 + i];
    }
    if (tid < 64)  b1s[tid] = f1b[m * 64 + tid];
    if (tid < 256) b2s[tid] = f2b[m * 256 + tid];
    for (int i = tid; i < 32 * 64; i += 256) {
        int t = i >> 6, f = i & 63;
        int l = l0 + t, c = m * 64 + f;
        xs[t * 65 + f] = x[(b * LL + l) * DD + c] + pe_val(l, c);
    }
    __syncthreads();

    int tx = tid & 63, ty = tid >> 6;   // tx = hidden idx; ty -> token subset
    float acc[8];
#pragma unroll
    for (int j = 0; j < 8; j++) acc[j] = b1s[tx];
#pragma unroll 8
    for (int f = 0; f < 64; f++) {
        float w = fc1s[f * 65 + tx];
#pragma unroll
        for (int j = 0; j < 8; j++)
            acc[j] += xs[(ty + 4 * j) * 65 + f] * w;
    }
#pragma unroll
    for (int j = 0; j < 8; j++) hs[(ty + 4 * j) * 65 + tx] = geluf(acc[j]);
    __syncthreads();

    float a2[8][4];
#pragma unroll
    for (int j = 0; j < 8; j++)
#pragma unroll
        for (int q = 0; q < 4; q++) a2[j][q] = b2s[tx + 64 * q];
#pragma unroll 8
    for (int h = 0; h < 64; h++) {
        float hv[8], wv[4];
#pragma unroll
        for (int j = 0; j < 8; j++) hv[j] = hs[(ty + 4 * j) * 65 + h];
#pragma unroll
        for (int q = 0; q < 4; q++) wv[q] = fc2s[h * 257 + tx + 64 * q];
#pragma unroll
        for (int j = 0; j < 8; j++)
#pragma unroll
            for (int q = 0; q < 4; q++)
                a2[j][q] += hv[j] * wv[q];
    }
#pragma unroll
    for (int j = 0; j < 8; j++) {
        int l = l0 + ty + 4 * j;
#pragma unroll
        for (int q = 0; q < 4; q++)
            Wout[((size_t)bm * LL + l) * KHH + tx + 64 * q] = a2[j][q];
    }
}

// ---------------- kernel 2: S = gelu(X^T @ W1), per (b,m) ----------------
// grid (4, 64); 256 threads; C tile 64d x 64n, K=2048 (l)
__global__ void __launch_bounds__(256)
bmm1_kernel(const float* __restrict__ x)
{
    __shared__ float4 As[32 * 16];  // [kl][d/4]
    __shared__ float4 Bs[32 * 16];  // [kl][n/4]
    int tid = threadIdx.x;
    int n0 = blockIdx.x * 64;
    int bm = blockIdx.y;
    int b = bm >> 3, m = bm & 7;
    int tx = tid & 15, ty = tid >> 4;
    float acc[4][4] = {};
    const float* W1 = g_W1 + (size_t)bm * LL * KHH;
    for (int k0 = 0; k0 < LL; k0 += 32) {
#pragma unroll
        for (int r = 0; r < 2; r++) {
            int q = tid + 256 * r;
            int kl = q >> 4, c4 = q & 15;
            As[q] = *(const float4*)&x[((size_t)(b * LL + k0 + kl)) * DD + m * 64 + c4 * 4];
            Bs[q] = *(const float4*)&W1[((size_t)(k0 + kl)) * KHH + n0 + c4 * 4];
        }
        __syncthreads();
#pragma unroll
        for (int kl = 0; kl < 32; kl++) {
            float4 a = As[kl * 16 + ty];
            float4 bb = Bs[kl * 16 + tx];
            float av[4] = {a.x, a.y, a.z, a.w};
            float bv[4] = {bb.x, bb.y, bb.z, bb.w};
#pragma unroll
            for (int i = 0; i < 4; i++)
#pragma unroll
                for (int j = 0; j < 4; j++)
                    acc[i][j] += av[i] * bv[j];
        }
        __syncthreads();
    }
    float* Sp = g_S + (size_t)bm * 64 * KHH;
#pragma unroll
    for (int i = 0; i < 4; i++) {
        int d = 4 * ty + i;
#pragma unroll
        for (int j = 0; j < 4; j++)
            Sp[d * KHH + n0 + 4 * tx + j] = geluf(acc[i][j]);
    }
}

// ---------------- kernel 3: out = S @ W2^T -> [B,L,D] (pre-LN) ----------------
// grid (32, 64); C tile 64d x 64l, K=256
__global__ void __launch_bounds__(256)
bmm2_kernel()
{
    __shared__ float Asm[64 * 33];
    __shared__ float Bsm[64 * 33];
    __shared__ float Cs[64 * 65];
    int tid = threadIdx.x;
    int l0 = blockIdx.x * 64;
    int bm = blockIdx.y;
    int b = bm >> 3, m = bm & 7;
    const float* Sp = g_S + (size_t)bm * 64 * KHH;
    const float* W2 = g_W2 + (size_t)bm * LL * KHH;
    int tx = tid & 15, ty = tid >> 4;
    float acc[4][4] = {};
    for (int k0 = 0; k0 < KHH; k0 += 32) {
#pragma unroll
        for (int r = 0; r < 8; r++) {
            int q = tid + 256 * r;
            int row = q >> 5, kk = q & 31;
            Asm[row * 33 + kk] = Sp[row * KHH + k0 + kk];
            Bsm[row * 33 + kk] = W2[((size_t)(l0 + row)) * KHH + k0 + kk];
        }
        __syncthreads();
#pragma unroll 8
        for (int kk = 0; kk < 32; kk++) {
            float av[4], bv[4];
#pragma unroll
            for (int i = 0; i < 4; i++) av[i] = Asm[(4 * ty + i) * 33 + kk];
#pragma unroll
            for (int j = 0; j < 4; j++) bv[j] = Bsm[(4 * tx + j) * 33 + kk];
#pragma unroll
            for (int i = 0; i < 4; i++)
#pragma unroll
                for (int j = 0; j < 4; j++)
                    acc[i][j] += av[i] * bv[j];
        }
        __syncthreads();
    }
#pragma unroll
    for (int j = 0; j < 4; j++)
#pragma unroll
        for (int i = 0; i < 4; i++)
            Cs[(4 * tx + j) * 65 + 4 * ty + i] = acc[i][j];
    __syncthreads();
#pragma unroll
    for (int r = 0; r < 16; r++) {
        int q = tid + 256 * r;
        int lr = q >> 6, d = q & 63;
        g_mixpre[((size_t)(b * LL + l0 + lr)) * DD + m * 64 + d] = Cs[lr * 65 + d];
    }
}

// ---------------- LN helpers ----------------
__device__ __forceinline__ float blk_sum128(float v, float* sbuf)
{
#pragma unroll
    for (int o = 16; o; o >>= 1) v += __shfl_xor_sync(0xffffffffu, v, o);
    __syncthreads();
    if ((threadIdx.x & 31) == 0) sbuf[threadIdx.x >> 5] = v;
    __syncthreads();
    return sbuf[0] + sbuf[1] + sbuf[2] + sbuf[3];
}

// kernel 4: mix = LN(mixpre) ; u = LN(mix)   (both stored)
__global__ void __launch_bounds__(128)
ln_mix_kernel(const float* __restrict__ g1, const float* __restrict__ b1,
              const float* __restrict__ g2, const float* __restrict__ b2)
{
    __shared__ float sbuf[4];
    size_t row = blockIdx.x;
    int t = threadIdx.x;
    const float* r = g_mixpre + row * DD;
    float v[4];
#pragma unroll
    for (int i = 0; i < 4; i++) v[i] = r[t + 128 * i];
    float mean = blk_sum128(v[0] + v[1] + v[2] + v[3], sbuf) * (1.0f / 512.0f);
    float sq = 0.f;
#pragma unroll
    for (int i = 0; i < 4; i++) { float d = v[i] - mean; sq += d * d; }
    float var = blk_sum128(sq, sbuf) * (1.0f / 512.0f);
    float inv = rsqrtf(var + 1e-5f);
    float mx[4];
#pragma unroll
    for (int i = 0; i < 4; i++) {
        int c = t + 128 * i;
        mx[i] = (v[i] - mean) * inv * g1[c] + b1[c];
        g_mix[row * DD + c] = mx[i];
    }
    float mean2 = blk_sum128(mx[0] + mx[1] + mx[2] + mx[3], sbuf) * (1.0f / 512.0f);
    float sq2 = 0.f;
#pragma unroll
    for (int i = 0; i < 4; i++) { float d = mx[i] - mean2; sq2 += d * d; }
    float var2 = blk_sum128(sq2, sbuf) * (1.0f / 512.0f);
    float inv2 = rsqrtf(var2 + 1e-5f);
#pragma unroll
    for (int i = 0; i < 4; i++) {
        int c = t + 128 * i;
        g_u[row * DD + c] = (mx[i] - mean2) * inv2 * g2[c] + b2[c];
    }
}

// ---------------- kernel 5: bottleneck 1x1 conv + GLU ----------------
// grid (8, 256); rows = flattened (b,l); cols n0..n0+63 pair with +512
__global__ void __launch_bounds__(256)
bneck_glu_kernel(const float* __restrict__ bw, const float* __restrict__ bb)
{
    __shared__ float Asm[64 * 33];
    __shared__ float Ba[64 * 33];
    __shared__ float Bb2[64 * 33];
    __shared__ float Cs[64 * 65];
    int tid = threadIdx.x;
    int n0 = blockIdx.x * 64;
    int r0 = blockIdx.y * 64;
    int tx = tid & 15, ty = tid >> 4;
    float aa[4][4] = {}, ab[4][4] = {};
    for (int k0 = 0; k0 < DD; k0 += 32) {
#pragma unroll
        for (int r = 0; r < 8; r++) {
            int q = tid + 256 * r;
            int row = q >> 5, kk = q & 31;
            Asm[row * 33 + kk] = g_u[((size_t)(r0 + row)) * DD + k0 + kk];
            Ba[row * 33 + kk]  = bw[((size_t)(n0 + row)) * DD + k0 + kk];
            Bb2[row * 33 + kk] = bw[((size_t)(512 + n0 + row)) * DD + k0 + kk];
        }
        __syncthreads();
#pragma unroll 8
        for (int kk = 0; kk < 32; kk++) {
            float av[4], b1v[4], b2v[4];
#pragma unroll
            for (int i = 0; i < 4; i++) av[i] = Asm[(4 * ty + i) * 33 + kk];
#pragma unroll
            for (int j = 0; j < 4; j++) {
                b1v[j] = Ba[(4 * tx + j) * 33 + kk];
                b2v[j] = Bb2[(4 * tx + j) * 33 + kk];
            }
#pragma unroll
            for (int i = 0; i < 4; i++)
#pragma unroll
                for (int j = 0; j < 4; j++) {
                    aa[i][j] += av[i] * b1v[j];
                    ab[i][j] += av[i] * b2v[j];
                }
        }
        __syncthreads();
    }
#pragma unroll
    for (int i = 0; i < 4; i++)
#pragma unroll
        for (int j = 0; j < 4; j++) {
            int c = n0 + 4 * tx + j;
            float ga = aa[i][j] + bb[c];
            float gb = ab[i][j] + bb[512 + c];
            Cs[(4 * ty + i) * 65 + 4 * tx + j] = ga * sigmoidf_(gb);
        }
    __syncthreads();
#pragma unroll
    for (int r = 0; r < 16; r++) {
        int q = tid + 256 * r;
        int rr = q >> 6, c = q & 63;
        g_c0[((size_t)(r0 + rr)) * DD + n0 + c] = Cs[rr * 65 + c];
    }
}

// ---------------- kernel 6: depthwise conv (K=31, pad 15) ----------------
// grid (8 chtile, 16 ltile, 8 b); 256 threads
__global__ void __launch_bounds__(256)
dwconv_kernel(const float* __restrict__ dw, const float* __restrict__ dwb)
{
    __shared__ float ins[158 * 64];
    __shared__ float wts[64 * 31];
    __shared__ float bs[64];
    int tid = threadIdx.x;
    int c0 = blockIdx.x * 64;
    int l0 = blockIdx.y * 128;
    int b  = blockIdx.z;
    for (int i = tid; i < 158 * 64; i += 256) {
        int rr = i >> 6, c = i & 63;
        int l = l0 - 15 + rr;
        ins[i] = (l >= 0 && l < LL) ? g_c0[((size_t)(b * LL + l)) * DD + c0 + c] : 0.f;
    }
    for (int i = tid; i < 64 * 31; i += 256)
        wts[i] = dw[c0 * 31 + i];
    if (tid < 64) bs[tid] = dwb[c0 + tid];
    __syncthreads();
    int tx = tid & 63, ty = tid >> 6;
    float w[31];
#pragma unroll
    for (int j = 0; j < 31; j++) w[j] = wts[tx * 31 + j];
    float bias = bs[tx];
    for (int li = 0; li < 32; li++) {
        int lr = ty * 32 + li;
        float acc = bias;
#pragma unroll
        for (int j = 0; j < 31; j++) acc += ins[(lr + j) * 64 + tx] * w[j];
        g_v[((size_t)(b * LL + l0 + lr)) * DD + c0 + tx] = acc;
    }
}

// ---------------- kernel 7: LN + gelu ----------------
__global__ void __launch_bounds__(128)
ln2_gelu_kernel(const float* __restrict__ g2, const float* __restrict__ b2)
{
    __shared__ float sbuf[4];
    size_t row = blockIdx.x;
    int t = threadIdx.x;
    const float* r = g_v + row * DD;
    float v[4];
#pragma unroll
    for (int i = 0; i < 4; i++) v[i] = r[t + 128 * i];
    float mean = blk_sum128(v[0] + v[1] + v[2] + v[3], sbuf) * (1.0f / 512.0f);
    float sq = 0.f;
#pragma unroll
    for (int i = 0; i < 4; i++) { float d = v[i] - mean; sq += d * d; }
    float var = blk_sum128(sq, sbuf) * (1.0f / 512.0f);
    float inv = rsqrtf(var + 1e-5f);
#pragma unroll
    for (int i = 0; i < 4; i++) {
        int c = t + 128 * i;
        g_w[row * DD + c] = geluf((v[i] - mean) * inv * g2[c] + b2[c]);
    }
}

// ---------------- kernel 8: final linear + bias + residual ----------------
// grid (8, 256)
__global__ void __launch_bounds__(256)
linear_res_kernel(const float* __restrict__ lw, const float* __restrict__ lb,
                  float* __restrict__ out)
{
    __shared__ float Asm[64 * 33];
    __shared__ float Bsm[64 * 33];
    __shared__ float Cs[64 * 65];
    int tid = threadIdx.x;
    int n0 = blockIdx.x * 64;
    int r0 = blockIdx.y * 64;
    int tx = tid & 15, ty = tid >> 4;
    float acc[4][4] = {};
    for (int k0 = 0; k0 < DD; k0 += 32) {
#pragma unroll
        for (int r = 0; r < 8; r++) {
            int q = tid + 256 * r;
            int row = q >> 5, kk = q & 31;
            Asm[row * 33 + kk] = g_w[((size_t)(r0 + row)) * DD + k0 + kk];
            Bsm[row * 33 + kk] = lw[((size_t)(n0 + row)) * DD + k0 + kk];
        }
        __syncthreads();
#pragma unroll 8
        for (int kk = 0; kk < 32; kk++) {
            float av[4], bv[4];
#pragma unroll
            for (int i = 0; i < 4; i++) av[i] = Asm[(4 * ty + i) * 33 + kk];
#pragma unroll
            for (int j = 0; j < 4; j++) bv[j] = Bsm[(4 * tx + j) * 33 + kk];
#pragma unroll
            for (int i = 0; i < 4; i++)
#pragma unroll
                for (int j = 0; j < 4; j++)
                    acc[i][j] += av[i] * bv[j];
        }
        __syncthreads();
    }
#pragma unroll
    for (int i = 0; i < 4; i++)
#pragma unroll
        for (int j = 0; j < 4; j++)
            Cs[(4 * ty + i) * 65 + 4 * tx + j] = acc[i][j] + lb[n0 + 4 * tx + j];
    __syncthreads();
#pragma unroll
    for (int r = 0; r < 16; r++) {
        int q = tid + 256 * r;
        int rr = q >> 6, c = q & 63;
        size_t idx = ((size_t)(r0 + rr)) * DD + n0 + c;
        out[idx] = Cs[rr * 65 + c] + g_mix[idx];
    }
}

// ---------------- launch ----------------
extern "C" void kernel_launch(void* const* d_in, const int* in_sizes, int n_in,
                              void* d_out, int out_size)
{
    (void)in_sizes; (void)n_in; (void)out_size;
    const float* x      = (const float*)d_in[0];
    const float* w1f1w  = (const float*)d_in[1];
    const float* w1f1b  = (const float*)d_in[2];
    const float* w1f2w  = (const float*)d_in[3];
    const float* w1f2b  = (const float*)d_in[4];
    const float* w2f1w  = (const float*)d_in[5];
    const float* w2f1b  = (const float*)d_in[6];
    const float* w2f2w  = (const float*)d_in[7];
    const float* w2f2b  = (const float*)d_in[8];
    const float* lnmg   = (const float*)d_in[9];
    const float* lnmb   = (const float*)d_in[10];
    const float* c1g    = (const float*)d_in[11];
    const float* c1b    = (const float*)d_in[12];
    const float* bw     = (const float*)d_in[13];
    const float* bb     = (const float*)d_in[14];
    const float* dww    = (const float*)d_in[15];
    const float* dwb    = (const float*)d_in[16];
    const float* c2g    = (const float*)d_in[17];
    const float* c2b    = (const float*)d_in[18];
    const float* lw     = (const float*)d_in[19];
    const float* lb     = (const float*)d_in[20];
    float* out = (float*)d_out;

    const int PMLP_SMEM = (64 * 65 + 64 * 257 + 64 + 256 + 32 * 65 + 32 * 65) * 4; // 100352
    cudaFuncSetAttribute(pmlp_kernel, cudaFuncAttributeMaxDynamicSharedMemorySize, PMLP_SMEM);

    pmlp_kernel<<<dim3(64, 64, 2), 256, PMLP_SMEM>>>(
        x, w1f1w, w1f1b, w1f2w, w1f2b, w2f1w, w2f1b, w2f2w, w2f2b);
    bmm1_kernel<<<dim3(4, 64), 256>>>(x);
    bmm2_kernel<<<dim3(32, 64), 256>>>();
    ln_mix_kernel<<<BB * LL, 128>>>(lnmg, lnmb, c1g, c1b);
    bneck_glu_kernel<<<dim3(8, 256), 256>>>(bw, bb);
    dwconv_kernel<<<dim3(8, 16, 8), 256>>>(dww, dwb);
    ln2_gelu_kernel<<<BB * LL, 128>>>(c2g, c2b);
    linear_res_kernel<<<dim3(8, 256), 256>>>(lw, lb, out);
}

// round 2
// speedup vs baseline: 2.0246x; 2.0246x over previous
#include <cuda_runtime.h>
#include <math.h>

#define BB 8
#define LL 2048
#define DD 512
#define MM 8
#define DHH 64
#define KHH 256

// ---------------- scratch (device globals; no allocations) ----------------
__device__ float g_H1[64 * 2048 * 64];       // [bm][l][h]  32MB
__device__ float g_H2[64 * 2048 * 64];       // [bm][l][h]  32MB
__device__ float g_T1p[4 * 64 * 64 * 64];    // [ks][bm][d][h] 4MB
__device__ float g_T2[64 * 64 * 64];         // [bm][d][h2] 1MB
__device__ float g_sb[64 * 64];              // [bm][d]
__device__ float g_mixpre[BB * LL * DD];
__device__ float g_mix[BB * LL * DD];
__device__ float g_u[BB * LL * DD];
__device__ float g_c0[BB * LL * DD];
__device__ float g_v[BB * LL * DD];
__device__ float g_w[BB * LL * DD];

__device__ __forceinline__ float geluf(float x) {
    return 0.5f * x * (1.0f + erff(x * 0.7071067811865476f));
}
__device__ __forceinline__ float sigmoidf_(float x) {
    return 1.0f / (1.0f + expf(-x));
}
__device__ __forceinline__ float pe_val(int l, int c) {
    float ang = (float)l * expf(-(float)(c & ~1) * 0.0179889460390160f);
    return (c & 1) ? cosf(ang) : sinf(ang);
}

// ============ kernel A: H = gelu(fc1(x + pe)) for both hyper-MLPs ============
// grid (32 ltiles, 64 bm, 2 which); 256 threads; tile 64l x 64h, K=64
__global__ void __launch_bounds__(256)
fc1_kernel(const float* __restrict__ x,
           const float* __restrict__ f1w_1, const float* __restrict__ f1b_1,
           const float* __restrict__ f1w_2, const float* __restrict__ f1b_2)
{
    __shared__ float Ws[64 * 65];   // [f][h]
    __shared__ float xs[64 * 65];   // [l][f]
    __shared__ float b1s[64];
    int tid = threadIdx.x;
    int l0 = blockIdx.x * 64;
    int bm = blockIdx.y;
    int b = bm >> 3, m = bm & 7;
    const float* f1w = blockIdx.z ? f1w_2 : f1w_1;
    const float* f1b = blockIdx.z ? f1b_2 : f1b_1;
    float* H = blockIdx.z ? g_H2 : g_H1;

    for (int i = tid; i < 4096; i += 256) {
        int h = i >> 6, f = i & 63;
        Ws[f * 65 + h] = f1w[m * 4096 + i];
    }
    if (tid < 64) b1s[tid] = f1b[m * 64 + tid];
    for (int i = tid; i < 4096; i += 256) {
        int lr = i >> 6, f = i & 63;
        int l = l0 + lr, c = m * 64 + f;
        xs[lr * 65 + f] = x[(size_t)(b * LL + l) * DD + c] + pe_val(l, c);
    }
    __syncthreads();

    int tx = tid & 15, ty = tid >> 4;
    float acc[4][4] = {};
#pragma unroll 8
    for (int f = 0; f < 64; f++) {
        float av[4], bv[4];
#pragma unroll
        for (int i = 0; i < 4; i++) av[i] = xs[(ty * 4 + i) * 65 + f];
#pragma unroll
        for (int j = 0; j < 4; j++) bv[j] = Ws[f * 65 + tx * 4 + j];
#pragma unroll
        for (int i = 0; i < 4; i++)
#pragma unroll
            for (int j = 0; j < 4; j++)
                acc[i][j] += av[i] * bv[j];
    }
#pragma unroll
    for (int i = 0; i < 4; i++) {
        int l = l0 + ty * 4 + i;
#pragma unroll
        for (int j = 0; j < 4; j++) {
            int h = tx * 4 + j;
            H[((size_t)bm * LL + l) * 64 + h] = geluf(acc[i][j] + b1s[h]);
        }
    }
}

// ============ kernel B: T1 partial = X_head^T @ H1 (K-split 4) ============
// grid (4 ks, 64 bm); 256 threads; out [64d x 64h]
__global__ void __launch_bounds__(256)
t1_kernel(const float* __restrict__ x)
{
    __shared__ float Xs[32 * 65];
    __shared__ float Hs[32 * 65];
    int tid = threadIdx.x;
    int ks = blockIdx.x, bm = blockIdx.y;
    int b = bm >> 3, m = bm & 7;
    int tx = tid & 15, ty = tid >> 4;
    float acc[4][4] = {};
    for (int kc = 0; kc < 16; kc++) {
        int lb = ks * 512 + kc * 32;
#pragma unroll
        for (int r = 0; r < 8; r++) {
            int i = tid + 256 * r;
            int kl = i >> 6, d = i & 63;
            Xs[kl * 65 + d] = x[(size_t)(b * LL + lb + kl) * DD + m * 64 + d];
            Hs[kl * 65 + d] = g_H1[((size_t)bm * LL + lb + kl) * 64 + d];
        }
        __syncthreads();
#pragma unroll 8
        for (int kl = 0; kl < 32; kl++) {
            float av[4], bv[4];
#pragma unroll
            for (int i = 0; i < 4; i++) av[i] = Xs[kl * 65 + ty * 4 + i];
#pragma unroll
            for (int j = 0; j < 4; j++) bv[j] = Hs[kl * 65 + tx * 4 + j];
#pragma unroll
            for (int i = 0; i < 4; i++)
#pragma unroll
                for (int j = 0; j < 4; j++)
                    acc[i][j] += av[i] * bv[j];
        }
        __syncthreads();
    }
#pragma unroll
    for (int i = 0; i < 4; i++)
#pragma unroll
        for (int j = 0; j < 4; j++)
            g_T1p[((size_t)(ks * 64 + bm)) * 4096 + (ty * 4 + i) * 64 + tx * 4 + j] = acc[i][j];
}

// ============ kernel C: reduce T1, xsum; S = gelu(T1 fc2_1^T + xsum*b2_1);
//              T2 = S fc2_2; sb = S.b2_2 ============
// grid (64 bm); 256 threads; dynamic smem
__global__ void __launch_bounds__(256)
sgen_kernel(const float* __restrict__ x,
            const float* __restrict__ f2w1, const float* __restrict__ f2b1,
            const float* __restrict__ f2w2, const float* __restrict__ f2b2)
{
    extern __shared__ float sm[];
    float* T1s  = sm;              // 64*65
    float* F1s  = T1s + 4160;      // 64*65 [khl][h]
    float* F2s  = F1s + 4160;      // 64*65 [khl][h2]
    float* Ss   = F2s + 4160;      // 64*65 [d][khl]
    float* xp   = Ss + 4160;       // 256
    float* xsums= xp + 256;        // 64
    float* b1s  = xsums + 64;      // 64
    float* b2s  = b1s + 64;        // 64
    int tid = threadIdx.x;
    int bm = blockIdx.x;
    int b = bm >> 3, m = bm & 7;

    // stage 1: reduce T1 partials
#pragma unroll
    for (int r = 0; r < 16; r++) {
        int o = tid + 256 * r;
        float s = 0.f;
#pragma unroll
        for (int ks = 0; ks < 4; ks++)
            s += g_T1p[((size_t)(ks * 64 + bm)) * 4096 + o];
        T1s[(o >> 6) * 65 + (o & 63)] = s;
    }
    // stage 2: column-sum of x head slice
    {
        int d = tid & 63, p = tid >> 6;
        const float* xp0 = &x[(size_t)(b * LL + p * 512) * DD + m * 64 + d];
        float s = 0.f;
        for (int l = 0; l < 512; l++) s += xp0[(size_t)l * DD];
        xp[p * 64 + d] = s;
    }
    __syncthreads();
    if (tid < 64) xsums[tid] = xp[tid] + xp[64 + tid] + xp[128 + tid] + xp[192 + tid];

    int tx = tid & 15, ty = tid >> 4;
    float t2acc[4][4] = {};
    float sbacc[4] = {};
    for (int c = 0; c < 4; c++) {
        __syncthreads();
#pragma unroll
        for (int r = 0; r < 16; r++) {
            int i = tid + 256 * r;
            int khl = i >> 6, h = i & 63;
            F1s[khl * 65 + h] = f2w1[(size_t)m * 16384 + (c * 64 + khl) * 64 + h];
            F2s[khl * 65 + h] = f2w2[(size_t)m * 16384 + (c * 64 + khl) * 64 + h];
        }
        if (tid < 64) {
            b1s[tid] = f2b1[m * 256 + c * 64 + tid];
            b2s[tid] = f2b2[m * 256 + c * 64 + tid];
        }
        __syncthreads();
        // S chunk: spre[d][khl] = sum_h T1[d,h]*F1[khl,h]
        float spre[4][4] = {};
#pragma unroll 8
        for (int h = 0; h < 64; h++) {
            float tv[4], fv[4];
#pragma unroll
            for (int ii = 0; ii < 4; ii++) tv[ii] = T1s[(ty * 4 + ii) * 65 + h];
#pragma unroll
            for (int jj = 0; jj < 4; jj++) fv[jj] = F1s[(tx * 4 + jj) * 65 + h];
#pragma unroll
            for (int ii = 0; ii < 4; ii++)
#pragma unroll
                for (int jj = 0; jj < 4; jj++)
                    spre[ii][jj] += tv[ii] * fv[jj];
        }
#pragma unroll
        for (int ii = 0; ii < 4; ii++)
#pragma unroll
            for (int jj = 0; jj < 4; jj++) {
                int d = ty * 4 + ii, khl = tx * 4 + jj;
                Ss[d * 65 + khl] = geluf(spre[ii][jj] + xsums[d] * b1s[khl]);
            }
        __syncthreads();
        // T2 += S_chunk @ F2_chunk ; sb += S_chunk . b2_chunk
#pragma unroll 8
        for (int khl = 0; khl < 64; khl++) {
            float sv[4], fv[4];
#pragma unroll
            for (int ii = 0; ii < 4; ii++) sv[ii] = Ss[(ty * 4 + ii) * 65 + khl];
#pragma unroll
            for (int jj = 0; jj < 4; jj++) fv[jj] = F2s[khl * 65 + tx * 4 + jj];
#pragma unroll
            for (int ii = 0; ii < 4; ii++)
#pragma unroll
                for (int jj = 0; jj < 4; jj++)
                    t2acc[ii][jj] += sv[ii] * fv[jj];
            if (tx == 0) {
                float bv = b2s[khl];
#pragma unroll
                for (int ii = 0; ii < 4; ii++) sbacc[ii] += sv[ii] * bv;
            }
        }
    }
#pragma unroll
    for (int ii = 0; ii < 4; ii++)
#pragma unroll
        for (int jj = 0; jj < 4; jj++)
            g_T2[(size_t)bm * 4096 + (ty * 4 + ii) * 64 + tx * 4 + jj] = t2acc[ii][jj];
    if (tx == 0)
#pragma unroll
        for (int ii = 0; ii < 4; ii++) g_sb[bm * 64 + ty * 4 + ii] = sbacc[ii];
}

// ============ kernel E: mixpre[l, d] = H2[l,:] . T2[d,:] + sb[d] ============
// grid (32 ltiles, 64 bm); 256 threads; tile 64l x 64d, K=64
__global__ void __launch_bounds__(256)
mixpre_kernel()
{
    __shared__ float Hs[64 * 65];   // [l][h]
    __shared__ float Ts[64 * 65];   // [d][h]
    __shared__ float sbs[64];
    int tid = threadIdx.x;
    int l0 = blockIdx.x * 64;
    int bm = blockIdx.y;
    int b = bm >> 3, m = bm & 7;
    for (int i = tid; i < 4096; i += 256) {
        int lr = i >> 6, h = i & 63;
        Hs[lr * 65 + h] = g_H2[((size_t)bm * LL + l0 + lr) * 64 + h];
        Ts[(i >> 6) * 65 + (i & 63)] = g_T2[(size_t)bm * 4096 + i];
    }
    if (tid < 64) sbs[tid] = g_sb[bm * 64 + tid];
    __syncthreads();
    int tx = tid & 15, ty = tid >> 4;
    float acc[4][4] = {};
#pragma unroll 8
    for (int h = 0; h < 64; h++) {
        float av[4], bv[4];
#pragma unroll
        for (int i = 0; i < 4; i++) av[i] = Hs[(ty * 4 + i) * 65 + h];
#pragma unroll
        for (int j = 0; j < 4; j++) bv[j] = Ts[(tx * 4 + j) * 65 + h];
#pragma unroll
        for (int i = 0; i < 4; i++)
#pragma unroll
            for (int j = 0; j < 4; j++)
                acc[i][j] += av[i] * bv[j];
    }
#pragma unroll
    for (int i = 0; i < 4; i++) {
        int l = l0 + ty * 4 + i;
#pragma unroll
        for (int j = 0; j < 4; j++) {
            int d = tx * 4 + j;
            g_mixpre[(size_t)(b * LL + l) * DD + m * 64 + d] = acc[i][j] + sbs[d];
        }
    }
}

// ---------------- LN helpers ----------------
__device__ __forceinline__ float blk_sum128(float v, float* sbuf)
{
#pragma unroll
    for (int o = 16; o; o >>= 1) v += __shfl_xor_sync(0xffffffffu, v, o);
    __syncthreads();
    if ((threadIdx.x & 31) == 0) sbuf[threadIdx.x >> 5] = v;
    __syncthreads();
    return sbuf[0] + sbuf[1] + sbuf[2] + sbuf[3];
}

// kernel: mix = LN(mixpre) ; u = LN(mix)
__global__ void __launch_bounds__(128)
ln_mix_kernel(const float* __restrict__ g1, const float* __restrict__ b1,
              const float* __restrict__ g2, const float* __restrict__ b2)
{
    __shared__ float sbuf[4];
    size_t row = blockIdx.x;
    int t = threadIdx.x;
    const float* r = g_mixpre + row * DD;
    float v[4];
#pragma unroll
    for (int i = 0; i < 4; i++) v[i] = r[t + 128 * i];
    float mean = blk_sum128(v[0] + v[1] + v[2] + v[3], sbuf) * (1.0f / 512.0f);
    float sq = 0.f;
#pragma unroll
    for (int i = 0; i < 4; i++) { float d = v[i] - mean; sq += d * d; }
    float var = blk_sum128(sq, sbuf) * (1.0f / 512.0f);
    float inv = rsqrtf(var + 1e-5f);
    float mx[4];
#pragma unroll
    for (int i = 0; i < 4; i++) {
        int c = t + 128 * i;
        mx[i] = (v[i] - mean) * inv * g1[c] + b1[c];
        g_mix[row * DD + c] = mx[i];
    }
    float mean2 = blk_sum128(mx[0] + mx[1] + mx[2] + mx[3], sbuf) * (1.0f / 512.0f);
    float sq2 = 0.f;
#pragma unroll
    for (int i = 0; i < 4; i++) { float d = mx[i] - mean2; sq2 += d * d; }
    float var2 = blk_sum128(sq2, sbuf) * (1.0f / 512.0f);
    float inv2 = rsqrtf(var2 + 1e-5f);
#pragma unroll
    for (int i = 0; i < 4; i++) {
        int c = t + 128 * i;
        g_u[row * DD + c] = (mx[i] - mean2) * inv2 * g2[c] + b2[c];
    }
}

// ============ bottleneck 1x1 + GLU : tile 128 rows x 64 cols, 8x4x2 ============
// grid (8 coltiles, 128 rowtiles)
__global__ void __launch_bounds__(256)
bneck_glu_kernel(const float* __restrict__ bw, const float* __restrict__ bb)
{
    __shared__ float As[16 * 132];
    __shared__ float Ba[16 * 68];
    __shared__ float Bb2[16 * 68];
    int tid = threadIdx.x;
    int n0 = blockIdx.x * 64;
    int r0 = blockIdx.y * 128;
    int tx = tid & 15, ty = tid >> 4;
    float ga[8][4] = {}, gb[8][4] = {};
    for (int k0 = 0; k0 < 512; k0 += 16) {
#pragma unroll
        for (int r = 0; r < 2; r++) {
            int u = tid * 2 + r;
            int row = u >> 2, kq = u & 3;
            float4 v = *(const float4*)&g_u[(size_t)(r0 + row) * 512 + k0 + kq * 4];
            As[(kq * 4 + 0) * 132 + row] = v.x;
            As[(kq * 4 + 1) * 132 + row] = v.y;
            As[(kq * 4 + 2) * 132 + row] = v.z;
            As[(kq * 4 + 3) * 132 + row] = v.w;
        }
        {
            int col = tid >> 2, kq = tid & 3;
            float4 v = *(const float4*)&bw[(size_t)(n0 + col) * 512 + k0 + kq * 4];
            Ba[(kq * 4 + 0) * 68 + col] = v.x;
            Ba[(kq * 4 + 1) * 68 + col] = v.y;
            Ba[(kq * 4 + 2) * 68 + col] = v.z;
            Ba[(kq * 4 + 3) * 68 + col] = v.w;
            float4 w = *(const float4*)&bw[(size_t)(512 + n0 + col) * 512 + k0 + kq * 4];
            Bb2[(kq * 4 + 0) * 68 + col] = w.x;
            Bb2[(kq * 4 + 1) * 68 + col] = w.y;
            Bb2[(kq * 4 + 2) * 68 + col] = w.z;
            Bb2[(kq * 4 + 3) * 68 + col] = w.w;
        }
        __syncthreads();
#pragma unroll
        for (int kk = 0; kk < 16; kk++) {
            float av[8], b1v[4], b2v[4];
            *(float4*)&av[0] = *(float4*)&As[kk * 132 + ty * 8];
            *(float4*)&av[4] = *(float4*)&As[kk * 132 + ty * 8 + 4];
            *(float4*)&b1v[0] = *(float4*)&Ba[kk * 68 + tx * 4];
            *(float4*)&b2v[0] = *(float4*)&Bb2[kk * 68 + tx * 4];
#pragma unroll
            for (int i = 0; i < 8; i++)
#pragma unroll
                for (int j = 0; j < 4; j++) {
                    ga[i][j] += av[i] * b1v[j];
                    gb[i][j] += av[i] * b2v[j];
                }
        }
        __syncthreads();
    }
#pragma unroll
    for (int i = 0; i < 8; i++) {
        float4 o;
        float* op = (float*)&o;
#pragma unroll
        for (int j = 0; j < 4; j++) {
            int c = n0 + tx * 4 + j;
            float a = ga[i][j] + bb[c];
            float bg = gb[i][j] + bb[512 + c];
            op[j] = a * sigmoidf_(bg);
        }
        *(float4*)&g_c0[(size_t)(r0 + ty * 8 + i) * 512 + n0 + tx * 4] = o;
    }
}

// ============ depthwise conv (K=31, pad 15) ============
__global__ void __launch_bounds__(256)
dwconv_kernel(const float* __restrict__ dw, const float* __restrict__ dwb)
{
    __shared__ float ins[158 * 64];
    __shared__ float wts[64 * 31];
    __shared__ float bs[64];
    int tid = threadIdx.x;
    int c0 = blockIdx.x * 64;
    int l0 = blockIdx.y * 128;
    int b  = blockIdx.z;
    for (int i = tid; i < 158 * 64; i += 256) {
        int rr = i >> 6, c = i & 63;
        int l = l0 - 15 + rr;
        ins[i] = (l >= 0 && l < LL) ? g_c0[((size_t)(b * LL + l)) * DD + c0 + c] : 0.f;
    }
    for (int i = tid; i < 64 * 31; i += 256)
        wts[i] = dw[c0 * 31 + i];
    if (tid < 64) bs[tid] = dwb[c0 + tid];
    __syncthreads();
    int tx = tid & 63, ty = tid >> 6;
    float w[31];
#pragma unroll
    for (int j = 0; j < 31; j++) w[j] = wts[tx * 31 + j];
    float bias = bs[tx];
    for (int li = 0; li < 32; li++) {
        int lr = ty * 32 + li;
        float acc = bias;
#pragma unroll
        for (int j = 0; j < 31; j++) acc += ins[(lr + j) * 64 + tx] * w[j];
        g_v[((size_t)(b * LL + l0 + lr)) * DD + c0 + tx] = acc;
    }
}

// ============ LN2 + gelu ============
__global__ void __launch_bounds__(128)
ln2_gelu_kernel(const float* __restrict__ g2, const float* __restrict__ b2)
{
    __shared__ float sbuf[4];
    size_t row = blockIdx.x;
    int t = threadIdx.x;
    const float* r = g_v + row * DD;
    float v[4];
#pragma unroll
    for (int i = 0; i < 4; i++) v[i] = r[t + 128 * i];
    float mean = blk_sum128(v[0] + v[1] + v[2] + v[3], sbuf) * (1.0f / 512.0f);
    float sq = 0.f;
#pragma unroll
    for (int i = 0; i < 4; i++) { float d = v[i] - mean; sq += d * d; }
    float var = blk_sum128(sq, sbuf) * (1.0f / 512.0f);
    float inv = rsqrtf(var + 1e-5f);
#pragma unroll
    for (int i = 0; i < 4; i++) {
        int c = t + 128 * i;
        g_w[row * DD + c] = geluf((v[i] - mean) * inv * g2[c] + b2[c]);
    }
}

// ============ final linear + bias + residual : 128x128 tile, 8x8 ============
// grid (4 coltiles, 128 rowtiles)
__global__ void __launch_bounds__(256)
linear_res_kernel(const float* __restrict__ lw, const float* __restrict__ lb,
                  float* __restrict__ out)
{
    __shared__ float As[16 * 132];
    __shared__ float Bs[16 * 132];
    int tid = threadIdx.x;
    int n0 = blockIdx.x * 128;
    int r0 = blockIdx.y * 128;
    int tx = tid & 15, ty = tid >> 4;
    float acc[8][8] = {};
    for (int k0 = 0; k0 < 512; k0 += 16) {
#pragma unroll
        for (int r = 0; r < 2; r++) {
            int u = tid * 2 + r;
            int row = u >> 2, kq = u & 3;
            float4 v = *(const float4*)&g_w[(size_t)(r0 + row) * 512 + k0 + kq * 4];
            As[(kq * 4 + 0) * 132 + row] = v.x;
            As[(kq * 4 + 1) * 132 + row] = v.y;
            As[(kq * 4 + 2) * 132 + row] = v.z;
            As[(kq * 4 + 3) * 132 + row] = v.w;
            float4 w = *(const float4*)&lw[(size_t)(n0 + row) * 512 + k0 + kq * 4];
            Bs[(kq * 4 + 0) * 132 + row] = w.x;
            Bs[(kq * 4 + 1) * 132 + row] = w.y;
            Bs[(kq * 4 + 2) * 132 + row] = w.z;
            Bs[(kq * 4 + 3) * 132 + row] = w.w;
        }
        __syncthreads();
#pragma unroll
        for (int kk = 0; kk < 16; kk++) {
            float av[8], bv[8];
            *(float4*)&av[0] = *(float4*)&As[kk * 132 + ty * 8];
            *(float4*)&av[4] = *(float4*)&As[kk * 132 + ty * 8 + 4];
            *(float4*)&bv[0] = *(float4*)&Bs[kk * 132 + tx * 8];
            *(float4*)&bv[4] = *(float4*)&Bs[kk * 132 + tx * 8 + 4];
#pragma unroll
            for (int i = 0; i < 8; i++)
#pragma unroll
                for (int j = 0; j < 8; j++)
                    acc[i][j] += av[i] * bv[j];
        }
        __syncthreads();
    }
#pragma unroll
    for (int i = 0; i < 8; i++) {
        size_t row = (size_t)(r0 + ty * 8 + i);
#pragma unroll
        for (int jj = 0; jj < 2; jj++) {
            float4 o;
            float* op = (float*)&o;
#pragma unroll
            for (int q = 0; q < 4; q++) {
                int c = n0 + tx * 8 + jj * 4 + q;
                size_t idx = row * 512 + c;
                op[q] = acc[i][jj * 4 + q] + lb[c] + g_mix[idx];
            }
            *(float4*)&out[row * 512 + n0 + tx * 8 + jj * 4] = o;
        }
    }
}

// ---------------- launch ----------------
extern "C" void kernel_launch(void* const* d_in, const int* in_sizes, int n_in,
                              void* d_out, int out_size)
{
    (void)in_sizes; (void)n_in; (void)out_size;
    const float* x      = (const float*)d_in[0];
    const float* w1f1w  = (const float*)d_in[1];
    const float* w1f1b  = (const float*)d_in[2];
    const float* w1f2w  = (const float*)d_in[3];
    const float* w1f2b  = (const float*)d_in[4];
    const float* w2f1w  = (const float*)d_in[5];
    const float* w2f1b  = (const float*)d_in[6];
    const float* w2f2w  = (const float*)d_in[7];
    const float* w2f2b  = (const float*)d_in[8];
    const float* lnmg   = (const float*)d_in[9];
    const float* lnmb   = (const float*)d_in[10];
    const float* c1g    = (const float*)d_in[11];
    const float* c1b    = (const float*)d_in[12];
    const float* bw     = (const float*)d_in[13];
    const float* bb     = (const float*)d_in[14];
    const float* dww    = (const float*)d_in[15];
    const float* dwb    = (const float*)d_in[16];
    const float* c2g    = (const float*)d_in[17];
    const float* c2b    = (const float*)d_in[18];
    const float* lw     = (const float*)d_in[19];
    const float* lb     = (const float*)d_in[20];
    float* out = (float*)d_out;

    const int SGEN_SMEM = (4 * 4160 + 256 + 64 + 64 + 64) * 4;  // ~68.3KB
    cudaFuncSetAttribute(sgen_kernel, cudaFuncAttributeMaxDynamicSharedMemorySize, SGEN_SMEM);

    fc1_kernel<<<dim3(32, 64, 2), 256>>>(x, w1f1w, w1f1b, w2f1w, w2f1b);
    t1_kernel<<<dim3(4, 64), 256>>>(x);
    sgen_kernel<<<64, 256, SGEN_SMEM>>>(x, w1f2w, w1f2b, w2f2w, w2f2b);
    mixpre_kernel<<<dim3(32, 64), 256>>>();
    ln_mix_kernel<<<BB * LL, 128>>>(lnmg, lnmb, c1g, c1b);
    bneck_glu_kernel<<<dim3(8, 128), 256>>>(bw, bb);
    dwconv_kernel<<<dim3(8, 16, 8), 256>>>(dww, dwb);
    ln2_gelu_kernel<<<BB * LL, 128>>>(c2g, c2b);
    linear_res_kernel<<<dim3(4, 128), 256>>>(lw, lb, out);
}

// round 5
// speedup vs baseline: 2.6666x; 1.3171x over previous
#include <cuda_runtime.h>
#include <math.h>
#include <stdint.h>

#define BB 8
#define LL 2048
#define DD 512
#define MM 8
#define DHH 64
#define KHH 256

// ---------------- scratch (device globals; no allocations) ----------------
__device__ float g_H1[64 * 2048 * 64];
__device__ float g_H2[64 * 2048 * 64];
__device__ float g_T1p[4 * 64 * 64 * 64];
__device__ float g_T2[64 * 64 * 64];
__device__ float g_sb[64 * 64];
__device__ float g_mixpre[BB * LL * DD];
__device__ float g_mix[BB * LL * DD];
__device__ float g_u[BB * LL * DD];
__device__ float g_c0[BB * LL * DD];
__device__ float g_v[BB * LL * DD];
__device__ float g_w[BB * LL * DD];

__device__ __forceinline__ float geluf(float x) {
    return 0.5f * x * (1.0f + erff(x * 0.7071067811865476f));
}
__device__ __forceinline__ float sigmoidf_(float x) {
    return 1.0f / (1.0f + expf(-x));
}
__device__ __forceinline__ float pe_val(int l, int c) {
    float ang = (float)l * expf(-(float)(c & ~1) * 0.0179889460390160f);
    return (c & 1) ? cosf(ang) : sinf(ang);
}
__device__ __forceinline__ float tf32r(float x) {
    uint32_t r;
    asm("cvt.rna.tf32.f32 %0, %1;" : "=r"(r) : "f"(x));
    return __uint_as_float(r);
}
__device__ __forceinline__ void mma_tf32(float* c, const uint32_t* a, const uint32_t* b)
{
    asm volatile(
        "mma.sync.aligned.m16n8k8.row.col.f32.tf32.tf32.f32 "
        "{%0,%1,%2,%3}, {%4,%5,%6,%7}, {%8,%9}, {%0,%1,%2,%3};\n"
        : "+f"(c[0]), "+f"(c[1]), "+f"(c[2]), "+f"(c[3])
        : "r"(a[0]), "r"(a[1]), "r"(a[2]), "r"(a[3]), "r"(b[0]), "r"(b[1]));
}

// ============ kernel A: H = gelu(fc1(x + pe)) for both hyper-MLPs ============
__global__ void __launch_bounds__(256)
fc1_kernel(const float* __restrict__ x,
           const float* __restrict__ f1w_1, const float* __restrict__ f1b_1,
           const float* __restrict__ f1w_2, const float* __restrict__ f1b_2)
{
    __shared__ float Ws[64 * 65];
    __shared__ float xs[64 * 65];
    __shared__ float b1s[64];
    int tid = threadIdx.x;
    int l0 = blockIdx.x * 64;
    int bm = blockIdx.y;
    int b = bm >> 3, m = bm & 7;
    const float* f1w = blockIdx.z ? f1w_2 : f1w_1;
    const float* f1b = blockIdx.z ? f1b_2 : f1b_1;
    float* H = blockIdx.z ? g_H2 : g_H1;

    for (int i = tid; i < 4096; i += 256) {
        int h = i >> 6, f = i & 63;
        Ws[f * 65 + h] = f1w[m * 4096 + i];
    }
    if (tid < 64) b1s[tid] = f1b[m * 64 + tid];
    for (int i = tid; i < 4096; i += 256) {
        int lr = i >> 6, f = i & 63;
        int l = l0 + lr, c = m * 64 + f;
        xs[lr * 65 + f] = x[(size_t)(b * LL + l) * DD + c] + pe_val(l, c);
    }
    __syncthreads();

    int tx = tid & 15, ty = tid >> 4;
    float acc[4][4] = {};
#pragma unroll 8
    for (int f = 0; f < 64; f++) {
        float av[4], bv[4];
#pragma unroll
        for (int i = 0; i < 4; i++) av[i] = xs[(ty * 4 + i) * 65 + f];
#pragma unroll
        for (int j = 0; j < 4; j++) bv[j] = Ws[f * 65 + tx * 4 + j];
#pragma unroll
        for (int i = 0; i < 4; i++)
#pragma unroll
            for (int j = 0; j < 4; j++)
                acc[i][j] += av[i] * bv[j];
    }
#pragma unroll
    for (int i = 0; i < 4; i++) {
        int l = l0 + ty * 4 + i;
#pragma unroll
        for (int j = 0; j < 4; j++) {
            int h = tx * 4 + j;
            H[((size_t)bm * LL + l) * 64 + h] = geluf(acc[i][j] + b1s[h]);
        }
    }
}

// ============ kernel B: T1 partial = X_head^T @ H1 (K-split 4) ============
__global__ void __launch_bounds__(256)
t1_kernel(const float* __restrict__ x)
{
    __shared__ float Xs[32 * 65];
    __shared__ float Hs[32 * 65];
    int tid = threadIdx.x;
    int ks = blockIdx.x, bm = blockIdx.y;
    int b = bm >> 3, m = bm & 7;
    int tx = tid & 15, ty = tid >> 4;
    float acc[4][4] = {};
    for (int kc = 0; kc < 16; kc++) {
        int lb = ks * 512 + kc * 32;
#pragma unroll
        for (int r = 0; r < 8; r++) {
            int i = tid + 256 * r;
            int kl = i >> 6, d = i & 63;
            Xs[kl * 65 + d] = x[(size_t)(b * LL + lb + kl) * DD + m * 64 + d];
            Hs[kl * 65 + d] = g_H1[((size_t)bm * LL + lb + kl) * 64 + d];
        }
        __syncthreads();
#pragma unroll 8
        for (int kl = 0; kl < 32; kl++) {
            float av[4], bv[4];
#pragma unroll
            for (int i = 0; i < 4; i++) av[i] = Xs[kl * 65 + ty * 4 + i];
#pragma unroll
            for (int j = 0; j < 4; j++) bv[j] = Hs[kl * 65 + tx * 4 + j];
#pragma unroll
            for (int i = 0; i < 4; i++)
#pragma unroll
                for (int j = 0; j < 4; j++)
                    acc[i][j] += av[i] * bv[j];
        }
        __syncthreads();
    }
#pragma unroll
    for (int i = 0; i < 4; i++)
#pragma unroll
        for (int j = 0; j < 4; j++)
            g_T1p[((size_t)(ks * 64 + bm)) * 4096 + (ty * 4 + i) * 64 + tx * 4 + j] = acc[i][j];
}

// ============ kernel C: T1 reduce; S = gelu(...); T2 = S fc2_2; sb = S.b2_2 ============
__global__ void __launch_bounds__(256)
sgen_kernel(const float* __restrict__ x,
            const float* __restrict__ f2w1, const float* __restrict__ f2b1,
            const float* __restrict__ f2w2, const float* __restrict__ f2b2)
{
    extern __shared__ float sm[];
    float* T1s  = sm;
    float* F1s  = T1s + 4160;
    float* F2s  = F1s + 4160;
    float* Ss   = F2s + 4160;
    float* xp   = Ss + 4160;
    float* xsums= xp + 256;
    float* b1s  = xsums + 64;
    float* b2s  = b1s + 64;
    int tid = threadIdx.x;
    int bm = blockIdx.x;
    int b = bm >> 3, m = bm & 7;

#pragma unroll
    for (int r = 0; r < 16; r++) {
        int o = tid + 256 * r;
        float s = 0.f;
#pragma unroll
        for (int ks = 0; ks < 4; ks++)
            s += g_T1p[((size_t)(ks * 64 + bm)) * 4096 + o];
        T1s[(o >> 6) * 65 + (o & 63)] = s;
    }
    {
        int d = tid & 63, p = tid >> 6;
        const float* xp0 = &x[(size_t)(b * LL + p * 512) * DD + m * 64 + d];
        float s = 0.f;
        for (int l = 0; l < 512; l++) s += xp0[(size_t)l * DD];
        xp[p * 64 + d] = s;
    }
    __syncthreads();
    if (tid < 64) xsums[tid] = xp[tid] + xp[64 + tid] + xp[128 + tid] + xp[192 + tid];

    int tx = tid & 15, ty = tid >> 4;
    float t2acc[4][4] = {};
    float sbacc[4] = {};
    for (int c = 0; c < 4; c++) {
        __syncthreads();
#pragma unroll
        for (int r = 0; r < 16; r++) {
            int i = tid + 256 * r;
            int khl = i >> 6, h = i & 63;
            F1s[khl * 65 + h] = f2w1[(size_t)m * 16384 + (c * 64 + khl) * 64 + h];
            F2s[khl * 65 + h] = f2w2[(size_t)m * 16384 + (c * 64 + khl) * 64 + h];
        }
        if (tid < 64) {
            b1s[tid] = f2b1[m * 256 + c * 64 + tid];
            b2s[tid] = f2b2[m * 256 + c * 64 + tid];
        }
        __syncthreads();
        float spre[4][4] = {};
#pragma unroll 8
        for (int h = 0; h < 64; h++) {
            float tv[4], fv[4];
#pragma unroll
            for (int ii = 0; ii < 4; ii++) tv[ii] = T1s[(ty * 4 + ii) * 65 + h];
#pragma unroll
            for (int jj = 0; jj < 4; jj++) fv[jj] = F1s[(tx * 4 + jj) * 65 + h];
#pragma unroll
            for (int ii = 0; ii < 4; ii++)
#pragma unroll
                for (int jj = 0; jj < 4; jj++)
                    spre[ii][jj] += tv[ii] * fv[jj];
        }
#pragma unroll
        for (int ii = 0; ii < 4; ii++)
#pragma unroll
            for (int jj = 0; jj < 4; jj++) {
                int d = ty * 4 + ii, khl = tx * 4 + jj;
                Ss[d * 65 + khl] = geluf(spre[ii][jj] + xsums[d] * b1s[khl]);
            }
        __syncthreads();
#pragma unroll 8
        for (int khl = 0; khl < 64; khl++) {
            float sv[4], fv[4];
#pragma unroll
            for (int ii = 0; ii < 4; ii++) sv[ii] = Ss[(ty * 4 + ii) * 65 + khl];
#pragma unroll
            for (int jj = 0; jj < 4; jj++) fv[jj] = F2s[khl * 65 + tx * 4 + jj];
#pragma unroll
            for (int ii = 0; ii < 4; ii++)
#pragma unroll
                for (int jj = 0; jj < 4; jj++)
                    t2acc[ii][jj] += sv[ii] * fv[jj];
            if (tx == 0) {
                float bv = b2s[khl];
#pragma unroll
                for (int ii = 0; ii < 4; ii++) sbacc[ii] += sv[ii] * bv;
            }
        }
    }
#pragma unroll
    for (int ii = 0; ii < 4; ii++)
#pragma unroll
        for (int jj = 0; jj < 4; jj++)
            g_T2[(size_t)bm * 4096 + (ty * 4 + ii) * 64 + tx * 4 + jj] = t2acc[ii][jj];
    if (tx == 0)
#pragma unroll
        for (int ii = 0; ii < 4; ii++) g_sb[bm * 64 + ty * 4 + ii] = sbacc[ii];
}

// ============ kernel E: mixpre = H2 . T2^T + sb ============
__global__ void __launch_bounds__(256)
mixpre_kernel()
{
    __shared__ float Hs[64 * 65];
    __shared__ float Ts[64 * 65];
    __shared__ float sbs[64];
    int tid = threadIdx.x;
    int l0 = blockIdx.x * 64;
    int bm = blockIdx.y;
    int b = bm >> 3, m = bm & 7;
    for (int i = tid; i < 4096; i += 256) {
        int lr = i >> 6, h = i & 63;
        Hs[lr * 65 + h] = g_H2[((size_t)bm * LL + l0 + lr) * 64 + h];
        Ts[(i >> 6) * 65 + (i & 63)] = g_T2[(size_t)bm * 4096 + i];
    }
    if (tid < 64) sbs[tid] = g_sb[bm * 64 + tid];
    __syncthreads();
    int tx = tid & 15, ty = tid >> 4;
    float acc[4][4] = {};
#pragma unroll 8
    for (int h = 0; h < 64; h++) {
        float av[4], bv[4];
#pragma unroll
        for (int i = 0; i < 4; i++) av[i] = Hs[(ty * 4 + i) * 65 + h];
#pragma unroll
        for (int j = 0; j < 4; j++) bv[j] = Ts[(tx * 4 + j) * 65 + h];
#pragma unroll
        for (int i = 0; i < 4; i++)
#pragma unroll
            for (int j = 0; j < 4; j++)
                acc[i][j] += av[i] * bv[j];
    }
#pragma unroll
    for (int i = 0; i < 4; i++) {
        int l = l0 + ty * 4 + i;
#pragma unroll
        for (int j = 0; j < 4; j++) {
            int d = tx * 4 + j;
            g_mixpre[(size_t)(b * LL + l) * DD + m * 64 + d] = acc[i][j] + sbs[d];
        }
    }
}

// ---------------- LN helpers ----------------
__device__ __forceinline__ float blk_sum128(float v, float* sbuf)
{
#pragma unroll
    for (int o = 16; o; o >>= 1) v += __shfl_xor_sync(0xffffffffu, v, o);
    __syncthreads();
    if ((threadIdx.x & 31) == 0) sbuf[threadIdx.x >> 5] = v;
    __syncthreads();
    return sbuf[0] + sbuf[1] + sbuf[2] + sbuf[3];
}

__global__ void __launch_bounds__(128)
ln_mix_kernel(const float* __restrict__ g1, const float* __restrict__ b1,
              const float* __restrict__ g2, const float* __restrict__ b2)
{
    __shared__ float sbuf[4];
    size_t row = blockIdx.x;
    int t = threadIdx.x;
    const float* r = g_mixpre + row * DD;
    float v[4];
#pragma unroll
    for (int i = 0; i < 4; i++) v[i] = r[t + 128 * i];
    float mean = blk_sum128(v[0] + v[1] + v[2] + v[3], sbuf) * (1.0f / 512.0f);
    float sq = 0.f;
#pragma unroll
    for (int i = 0; i < 4; i++) { float d = v[i] - mean; sq += d * d; }
    float var = blk_sum128(sq, sbuf) * (1.0f / 512.0f);
    float inv = rsqrtf(var + 1e-5f);
    float mx[4];
#pragma unroll
    for (int i = 0; i < 4; i++) {
        int c = t + 128 * i;
        mx[i] = (v[i] - mean) * inv * g1[c] + b1[c];
        g_mix[row * DD + c] = mx[i];
    }
    float mean2 = blk_sum128(mx[0] + mx[1] + mx[2] + mx[3], sbuf) * (1.0f / 512.0f);
    float sq2 = 0.f;
#pragma unroll
    for (int i = 0; i < 4; i++) { float d = mx[i] - mean2; sq2 += d * d; }
    float var2 = blk_sum128(sq2, sbuf) * (1.0f / 512.0f);
    float inv2 = rsqrtf(var2 + 1e-5f);
#pragma unroll
    for (int i = 0; i < 4; i++) {
        int c = t + 128 * i;
        g_u[row * DD + c] = (mx[i] - mean2) * inv2 * g2[c] + b2[c];
    }
}

// ============ bottleneck 1x1 + GLU via tf32 mma ============
// block 128 rows x 64 real cols (128 virtual: even=ga, odd=gb). 8 warps (4m x 2n).
__global__ void __launch_bounds__(256)
bneck_glu_mma(const float* __restrict__ bw, const float* __restrict__ bb)
{
    __shared__ float As[16][132];   // [k][row]
    __shared__ float Bs[16][132];   // [k][vcol]
    __shared__ float Cs[32][68];    // epilogue staging
    int tid = threadIdx.x;
    int warp = tid >> 5, lane = tid & 31;
    int mw = warp & 3, nw = warp >> 2;
    int gid = lane >> 2, tig = lane & 3;
    int r0 = blockIdx.y * 128, n0 = blockIdx.x * 64;

    float acc[2][8][4];
#pragma unroll
    for (int mi = 0; mi < 2; mi++)
#pragma unroll
        for (int ni = 0; ni < 8; ni++)
#pragma unroll
            for (int q = 0; q < 4; q++) acc[mi][ni][q] = 0.f;

    int arow = tid >> 1;            // 0..127
    int akq  = (tid & 1) * 8;       // 0 or 8
    int vcol = tid >> 1;
    int brr  = (vcol & 1) ? (512 + n0 + (vcol >> 1)) : (n0 + (vcol >> 1));

    for (int k0 = 0; k0 < 512; k0 += 16) {
        // load A tile
        {
            const float* p = &g_u[(size_t)(r0 + arow) * 512 + k0 + akq];
            float4 v0 = *(const float4*)p;
            float4 v1 = *(const float4*)(p + 4);
            As[akq + 0][arow] = tf32r(v0.x); As[akq + 1][arow] = tf32r(v0.y);
            As[akq + 2][arow] = tf32r(v0.z); As[akq + 3][arow] = tf32r(v0.w);
            As[akq + 4][arow] = tf32r(v1.x); As[akq + 5][arow] = tf32r(v1.y);
            As[akq + 6][arow] = tf32r(v1.z); As[akq + 7][arow] = tf32r(v1.w);
        }
        // load B tile (interleaved gates)
        {
            const float* p = &bw[(size_t)brr * 512 + k0 + akq];
            float4 v0 = *(const float4*)p;
            float4 v1 = *(const float4*)(p + 4);
            Bs[akq + 0][vcol] = tf32r(v0.x); Bs[akq + 1][vcol] = tf32r(v0.y);
            Bs[akq + 2][vcol] = tf32r(v0.z); Bs[akq + 3][vcol] = tf32r(v0.w);
            Bs[akq + 4][vcol] = tf32r(v1.x); Bs[akq + 5][vcol] = tf32r(v1.y);
            Bs[akq + 6][vcol] = tf32r(v1.z); Bs[akq + 7][vcol] = tf32r(v1.w);
        }
        __syncthreads();
#pragma unroll
        for (int kk = 0; kk < 16; kk += 8) {
            uint32_t a[2][4];
#pragma unroll
            for (int mi = 0; mi < 2; mi++) {
                int rb = mw * 32 + mi * 16;
                a[mi][0] = __float_as_uint(As[kk + tig][rb + gid]);
                a[mi][1] = __float_as_uint(As[kk + tig][rb + gid + 8]);
                a[mi][2] = __float_as_uint(As[kk + tig + 4][rb + gid]);
                a[mi][3] = __float_as_uint(As[kk + tig + 4][rb + gid + 8]);
            }
            uint32_t bfr[8][2];
#pragma unroll
            for (int ni = 0; ni < 8; ni++) {
                int vb = nw * 64 + ni * 8;
                bfr[ni][0] = __float_as_uint(Bs[kk + tig][vb + gid]);
                bfr[ni][1] = __float_as_uint(Bs[kk + tig + 4][vb + gid]);
            }
#pragma unroll
            for (int mi = 0; mi < 2; mi++)
#pragma unroll
                for (int ni = 0; ni < 8; ni++)
                    mma_tf32(acc[mi][ni], a[mi], bfr[ni]);
        }
        __syncthreads();
    }

    // per-thread real col for each ni frag: cR = n0 + nw*32 + ni*4 + tig
    float bbA[8], bbB[8];
#pragma unroll
    for (int ni = 0; ni < 8; ni++) {
        int cR = n0 + nw * 32 + ni * 4 + tig;
        bbA[ni] = bb[cR];
        bbB[ni] = bb[512 + cR];
    }
    // epilogue: 4 passes of 32 rows staged through Cs
    for (int p = 0; p < 4; p++) {
        if (mw == p) {
#pragma unroll
            for (int mi = 0; mi < 2; mi++)
#pragma unroll
                for (int ni = 0; ni < 8; ni++) {
                    int cc = nw * 32 + ni * 4 + tig;
                    float ga0 = acc[mi][ni][0] + bbA[ni];
                    float gb0 = acc[mi][ni][1] + bbB[ni];
                    float ga1 = acc[mi][ni][2] + bbA[ni];
                    float gb1 = acc[mi][ni][3] + bbB[ni];
                    Cs[mi * 16 + gid][cc]     = ga0 * sigmoidf_(gb0);
                    Cs[mi * 16 + gid + 8][cc] = ga1 * sigmoidf_(gb1);
                }
        }
        __syncthreads();
        {
            int row = tid >> 3, c = (tid & 7) * 8;
            float4 v0 = *(float4*)&Cs[row][c];
            float4 v1 = *(float4*)&Cs[row][c + 4];
            float* op = &g_c0[(size_t)(r0 + p * 32 + row) * 512 + n0 + c];
            *(float4*)op = v0;
            *(float4*)(op + 4) = v1;
        }
        __syncthreads();
    }
}

// ============ depthwise conv (K=31, pad 15) ============
__global__ void __launch_bounds__(256)
dwconv_kernel(const float* __restrict__ dw, const float* __restrict__ dwb)
{
    __shared__ float ins[158 * 64];
    __shared__ float wts[64 * 31];
    __shared__ float bs[64];
    int tid = threadIdx.x;
    int c0 = blockIdx.x * 64;
    int l0 = blockIdx.y * 128;
    int b  = blockIdx.z;
    for (int i = tid; i < 158 * 64; i += 256) {
        int rr = i >> 6, c = i & 63;
        int l = l0 - 15 + rr;
        ins[i] = (l >= 0 && l < LL) ? g_c0[((size_t)(b * LL + l)) * DD + c0 + c] : 0.f;
    }
    for (int i = tid; i < 64 * 31; i += 256)
        wts[i] = dw[c0 * 31 + i];
    if (tid < 64) bs[tid] = dwb[c0 + tid];
    __syncthreads();
    int tx = tid & 63, ty = tid >> 6;
    float w[31];
#pragma unroll
    for (int j = 0; j < 31; j++) w[j] = wts[tx * 31 + j];
    float bias = bs[tx];
    for (int li = 0; li < 32; li++) {
        int lr = ty * 32 + li;
        float acc = bias;
#pragma unroll
        for (int j = 0; j < 31; j++) acc += ins[(lr + j) * 64 + tx] * w[j];
        g_v[((size_t)(b * LL + l0 + lr)) * DD + c0 + tx] = acc;
    }
}

// ============ LN2 + gelu ============
__global__ void __launch_bounds__(128)
ln2_gelu_kernel(const float* __restrict__ g2, const float* __restrict__ b2)
{
    __shared__ float sbuf[4];
    size_t row = blockIdx.x;
    int t = threadIdx.x;
    const float* r = g_v + row * DD;
    float v[4];
#pragma unroll
    for (int i = 0; i < 4; i++) v[i] = r[t + 128 * i];
    float mean = blk_sum128(v[0] + v[1] + v[2] + v[3], sbuf) * (1.0f / 512.0f);
    float sq = 0.f;
#pragma unroll
    for (int i = 0; i < 4; i++) { float d = v[i] - mean; sq += d * d; }
    float var = blk_sum128(sq, sbuf) * (1.0f / 512.0f);
    float inv = rsqrtf(var + 1e-5f);
#pragma unroll
    for (int i = 0; i < 4; i++) {
        int c = t + 128 * i;
        g_w[row * DD + c] = geluf((v[i] - mean) * inv * g2[c] + b2[c]);
    }
}

// ============ final linear + bias + residual via tf32 mma ============
// block 128 rows x 128 cols. 8 warps (4m x 2n).
__global__ void __launch_bounds__(256)
linear_res_mma(const float* __restrict__ lw, const float* __restrict__ lb,
               float* __restrict__ out)
{
    __shared__ float As[16][132];
    __shared__ float Bs[16][132];
    __shared__ float Cs[32][132];
    int tid = threadIdx.x;
    int warp = tid >> 5, lane = tid & 31;
    int mw = warp & 3, nw = warp >> 2;
    int gid = lane >> 2, tig = lane & 3;
    int r0 = blockIdx.y * 128, n0 = blockIdx.x * 128;

    float acc[2][8][4];
#pragma unroll
    for (int mi = 0; mi < 2; mi++)
#pragma unroll
        for (int ni = 0; ni < 8; ni++)
#pragma unroll
            for (int q = 0; q < 4; q++) acc[mi][ni][q] = 0.f;

    int arow = tid >> 1;
    int akq  = (tid & 1) * 8;

    for (int k0 = 0; k0 < 512; k0 += 16) {
        {
            const float* p = &g_w[(size_t)(r0 + arow) * 512 + k0 + akq];
            float4 v0 = *(const float4*)p;
            float4 v1 = *(const float4*)(p + 4);
            As[akq + 0][arow] = tf32r(v0.x); As[akq + 1][arow] = tf32r(v0.y);
            As[akq + 2][arow] = tf32r(v0.z); As[akq + 3][arow] = tf32r(v0.w);
            As[akq + 4][arow] = tf32r(v1.x); As[akq + 5][arow] = tf32r(v1.y);
            As[akq + 6][arow] = tf32r(v1.z); As[akq + 7][arow] = tf32r(v1.w);
        }
        {
            const float* p = &lw[(size_t)(n0 + arow) * 512 + k0 + akq];
            float4 v0 = *(const float4*)p;
            float4 v1 = *(const float4*)(p + 4);
            Bs[akq + 0][arow] = tf32r(v0.x); Bs[akq + 1][arow] = tf32r(v0.y);
            Bs[akq + 2][arow] = tf32r(v0.z); Bs[akq + 3][arow] = tf32r(v0.w);
            Bs[akq + 4][arow] = tf32r(v1.x); Bs[akq + 5][arow] = tf32r(v1.y);
            Bs[akq + 6][arow] = tf32r(v1.z); Bs[akq + 7][arow] = tf32r(v1.w);
        }
        __syncthreads();
#pragma unroll
        for (int kk = 0; kk < 16; kk += 8) {
            uint32_t a[2][4];
#pragma unroll
            for (int mi = 0; mi < 2; mi++) {
                int rb = mw * 32 + mi * 16;
                a[mi][0] = __float_as_uint(As[kk + tig][rb + gid]);
                a[mi][1] = __float_as_uint(As[kk + tig][rb + gid + 8]);
                a[mi][2] = __float_as_uint(As[kk + tig + 4][rb + gid]);
                a[mi][3] = __float_as_uint(As[kk + tig + 4][rb + gid + 8]);
            }
            uint32_t bfr[8][2];
#pragma unroll
            for (int ni = 0; ni < 8; ni++) {
                int vb = nw * 64 + ni * 8;
                bfr[ni][0] = __float_as_uint(Bs[kk + tig][vb + gid]);
                bfr[ni][1] = __float_as_uint(Bs[kk + tig + 4][vb + gid]);
            }
#pragma unroll
            for (int mi = 0; mi < 2; mi++)
#pragma unroll
                for (int ni = 0; ni < 8; ni++)
                    mma_tf32(acc[mi][ni], a[mi], bfr[ni]);
        }
        __syncthreads();
    }

    for (int p = 0; p < 4; p++) {
        if (mw == p) {
#pragma unroll
            for (int mi = 0; mi < 2; mi++)
#pragma unroll
                for (int ni = 0; ni < 8; ni++) {
                    int cc = nw * 64 + ni * 8 + tig * 2;
                    Cs[mi * 16 + gid][cc]         = acc[mi][ni][0];
                    Cs[mi * 16 + gid][cc + 1]     = acc[mi][ni][1];
                    Cs[mi * 16 + gid + 8][cc]     = acc[mi][ni][2];
                    Cs[mi * 16 + gid + 8][cc + 1] = acc[mi][ni][3];
                }
        }
        __syncthreads();
        {
            int row = tid >> 3, c0c = (tid & 7) * 16;
            size_t gro = (size_t)(r0 + p * 32 + row) * 512 + n0;
#pragma unroll
            for (int q = 0; q < 4; q++) {
                int c = c0c + q * 4;
                float4 v = *(float4*)&Cs[row][c];
                float4 mres = *(const float4*)&g_mix[gro + c];
                float4 bl = *(const float4*)&lb[n0 + c];
                v.x += bl.x + mres.x; v.y += bl.y + mres.y;
                v.z += bl.z + mres.z; v.w += bl.w + mres.w;
                *(float4*)&out[gro + c] = v;
            }
        }
        __syncthreads();
    }
}

// ---------------- launch ----------------
extern "C" void kernel_launch(void* const* d_in, const int* in_sizes, int n_in,
                              void* d_out, int out_size)
{
    (void)in_sizes; (void)n_in; (void)out_size;
    const float* x      = (const float*)d_in[0];
    const float* w1f1w  = (const float*)d_in[1];
    const float* w1f1b  = (const float*)d_in[2];
    const float* w1f2w  = (const float*)d_in[3];
    const float* w1f2b  = (const float*)d_in[4];
    const float* w2f1w  = (const float*)d_in[5];
    const float* w2f1b  = (const float*)d_in[6];
    const float* w2f2w  = (const float*)d_in[7];
    const float* w2f2b  = (const float*)d_in[8];
    const float* lnmg   = (const float*)d_in[9];
    const float* lnmb   = (const float*)d_in[10];
    const float* c1g    = (const float*)d_in[11];
    const float* c1b    = (const float*)d_in[12];
    const float* bw     = (const float*)d_in[13];
    const float* bb     = (const float*)d_in[14];
    const float* dww    = (const float*)d_in[15];
    const float* dwb    = (const float*)d_in[16];
    const float* c2g    = (const float*)d_in[17];
    const float* c2b    = (const float*)d_in[18];
    const float* lw     = (const float*)d_in[19];
    const float* lb     = (const float*)d_in[20];
    float* out = (float*)d_out;

    const int SGEN_SMEM = (4 * 4160 + 256 + 64 + 64 + 64) * 4;
    cudaFuncSetAttribute(sgen_kernel, cudaFuncAttributeMaxDynamicSharedMemorySize, SGEN_SMEM);

    fc1_kernel<<<dim3(32, 64, 2), 256>>>(x, w1f1w, w1f1b, w2f1w, w2f1b);
    t1_kernel<<<dim3(4, 64), 256>>>(x);
    sgen_kernel<<<64, 256, SGEN_SMEM>>>(x, w1f2w, w1f2b, w2f2w, w2f2b);
    mixpre_kernel<<<dim3(32, 64), 256>>>();
    ln_mix_kernel<<<BB * LL, 128>>>(lnmg, lnmb, c1g, c1b);
    bneck_glu_mma<<<dim3(8, 128), 256>>>(bw, bb);
    dwconv_kernel<<<dim3(8, 16, 8), 256>>>(dww, dwb);
    ln2_gelu_kernel<<<BB * LL, 128>>>(c2g, c2b);
    linear_res_mma<<<dim3(4, 128), 256>>>(lw, lb, out);
}

// round 6
// speedup vs baseline: 2.9601x; 1.1101x over previous
#include <cuda_runtime.h>
#include <math.h>
#include <stdint.h>

#define BB 8
#define LL 2048
#define DD 512
#define MM 8
#define DHH 64
#define KHH 256

// ---------------- scratch (device globals; no allocations) ----------------
__device__ float g_H1[64 * 2048 * 64];
__device__ float g_H2[64 * 2048 * 64];
__device__ float g_T1p[4 * 64 * 64 * 64];
__device__ float g_T2[64 * 64 * 64];
__device__ float g_sb[64 * 64];
__device__ float g_mixpre[BB * LL * DD];
__device__ float g_mix[BB * LL * DD];
__device__ float g_u[BB * LL * DD];
__device__ float g_c0[BB * LL * DD];
__device__ float g_v[BB * LL * DD];
__device__ float g_w[BB * LL * DD];

__device__ __forceinline__ float geluf(float x) {
    return 0.5f * x * (1.0f + erff(x * 0.7071067811865476f));
}
__device__ __forceinline__ float sigmoidf_(float x) {
    return 1.0f / (1.0f + expf(-x));
}
__device__ __forceinline__ float pe_val(int l, int c) {
    float ang = (float)l * expf(-(float)(c & ~1) * 0.0179889460390160f);
    return (c & 1) ? cosf(ang) : sinf(ang);
}
__device__ __forceinline__ float tf32r(float x) {
    uint32_t r;
    asm("cvt.rna.tf32.f32 %0, %1;" : "=r"(r) : "f"(x));
    return __uint_as_float(r);
}
__device__ __forceinline__ void split3(float v, uint32_t& hi, uint32_t& lo) {
    uint32_t h;
    asm("cvt.rna.tf32.f32 %0, %1;" : "=r"(h) : "f"(v));
    float r = v - __uint_as_float(h);
    uint32_t l;
    asm("cvt.rna.tf32.f32 %0, %1;" : "=r"(l) : "f"(r));
    hi = h; lo = l;
}
__device__ __forceinline__ void mma_tf32(float* c, const uint32_t* a, const uint32_t* b)
{
    asm volatile(
        "mma.sync.aligned.m16n8k8.row.col.f32.tf32.tf32.f32 "
        "{%0,%1,%2,%3}, {%4,%5,%6,%7}, {%8,%9}, {%0,%1,%2,%3};\n"
        : "+f"(c[0]), "+f"(c[1]), "+f"(c[2]), "+f"(c[3])
        : "r"(a[0]), "r"(a[1]), "r"(a[2]), "r"(a[3]), "r"(b[0]), "r"(b[1]));
}

// ============ kernel A: H1,H2 = gelu(fc1_{1,2}(x + pe)) — 3xTF32 mma ============
// grid (16 ltiles, 64 bm); 256 threads; block 128l x 64h, K=64, both MLPs
__global__ void __launch_bounds__(256)
fc1_mma(const float* __restrict__ x,
        const float* __restrict__ f1w_1, const float* __restrict__ f1b_1,
        const float* __restrict__ f1w_2, const float* __restrict__ f1b_2)
{
    extern __shared__ float sm[];
    float* Xs  = sm;                 // [128][68]
    float* W1s = Xs + 128 * 68;      // [64][68]  [h][f]
    float* W2s = W1s + 64 * 68;      // [64][68]
    float* Cs  = W2s + 64 * 68;      // [64][68]
    float* b1s = Cs + 64 * 68;       // 64
    float* b2s = b1s + 64;           // 64
    int tid = threadIdx.x;
    int l0 = blockIdx.x * 128;
    int bm = blockIdx.y;
    int b = bm >> 3, m = bm & 7;

    {
        int f4 = (tid & 15) * 4, r = tid >> 4;
#pragma unroll
        for (int it = 0; it < 8; it++) {
            int row = r + it * 16;
            int l = l0 + row;
            float4 v = *(const float4*)&x[(size_t)(b * LL + l) * DD + m * 64 + f4];
            Xs[row * 68 + f4 + 0] = v.x + pe_val(l, m * 64 + f4 + 0);
            Xs[row * 68 + f4 + 1] = v.y + pe_val(l, m * 64 + f4 + 1);
            Xs[row * 68 + f4 + 2] = v.z + pe_val(l, m * 64 + f4 + 2);
            Xs[row * 68 + f4 + 3] = v.w + pe_val(l, m * 64 + f4 + 3);
        }
#pragma unroll
        for (int it = 0; it < 4; it++) {
            int hh = r + it * 16;
            *(float4*)&W1s[hh * 68 + f4] = *(const float4*)&f1w_1[m * 4096 + hh * 64 + f4];
            *(float4*)&W2s[hh * 68 + f4] = *(const float4*)&f1w_2[m * 4096 + hh * 64 + f4];
        }
        if (tid < 64) { b1s[tid] = f1b_1[m * 64 + tid]; b2s[tid] = f1b_2[m * 64 + tid]; }
    }
    __syncthreads();

    int warp = tid >> 5, lane = tid & 31, gid = lane >> 2, tig = lane & 3;
    int mw = warp & 3, nw = warp >> 2;
    int rb = mw * 32, vb = nw * 32;

    for (int which = 0; which < 2; which++) {
        const float* Ws = which ? W2s : W1s;
        const float* bs = which ? b2s : b1s;
        float* H = which ? g_H2 : g_H1;
        float acc[2][4][4] = {};
#pragma unroll
        for (int kk = 0; kk < 64; kk += 8) {
            uint32_t ah[2][4], al[2][4];
#pragma unroll
            for (int mi = 0; mi < 2; mi++) {
                int rr = rb + mi * 16;
                split3(Xs[(rr + gid) * 68 + kk + tig],     ah[mi][0], al[mi][0]);
                split3(Xs[(rr + gid + 8) * 68 + kk + tig], ah[mi][1], al[mi][1]);
                split3(Xs[(rr + gid) * 68 + kk + tig + 4],     ah[mi][2], al[mi][2]);
                split3(Xs[(rr + gid + 8) * 68 + kk + tig + 4], ah[mi][3], al[mi][3]);
            }
            uint32_t bh[4][2], bl[4][2];
#pragma unroll
            for (int ni = 0; ni < 4; ni++) {
                int cc = vb + ni * 8 + gid;
                split3(Ws[cc * 68 + kk + tig],     bh[ni][0], bl[ni][0]);
                split3(Ws[cc * 68 + kk + tig + 4], bh[ni][1], bl[ni][1]);
            }
#pragma unroll
            for (int mi = 0; mi < 2; mi++)
#pragma unroll
                for (int ni = 0; ni < 4; ni++) {
                    mma_tf32(acc[mi][ni], ah[mi], bh[ni]);
                    mma_tf32(acc[mi][ni], ah[mi], bl[ni]);
                    mma_tf32(acc[mi][ni], al[mi], bh[ni]);
                }
        }
#pragma unroll
        for (int p = 0; p < 2; p++) {
            if ((mw >> 1) == p) {
                int lr = (mw & 1) * 32;
#pragma unroll
                for (int mi = 0; mi < 2; mi++)
#pragma unroll
                    for (int ni = 0; ni < 4; ni++) {
                        int rr = lr + mi * 16 + gid;
                        int cc = vb + ni * 8 + tig * 2;
                        Cs[rr * 68 + cc]           = geluf(acc[mi][ni][0] + bs[cc]);
                        Cs[rr * 68 + cc + 1]       = geluf(acc[mi][ni][1] + bs[cc + 1]);
                        Cs[(rr + 8) * 68 + cc]     = geluf(acc[mi][ni][2] + bs[cc]);
                        Cs[(rr + 8) * 68 + cc + 1] = geluf(acc[mi][ni][3] + bs[cc + 1]);
                    }
            }
            __syncthreads();
#pragma unroll
            for (int it = 0; it < 4; it++) {
                int idx = tid + 256 * it;
                int row = idx >> 4, c4 = (idx & 15) * 4;
                *(float4*)&H[((size_t)bm * LL + l0 + p * 64 + row) * 64 + c4] =
                    *(float4*)&Cs[row * 68 + c4];
            }
            __syncthreads();
        }
    }
}

// ============ kernel B: T1 partial = X_head^T @ H1 (K-split 4) — 3xTF32 mma ============
// grid (4 ks, 64 bm); out [64d x 64h], K=512 per block
__global__ void __launch_bounds__(256)
t1_mma(const float* __restrict__ x)
{
    __shared__ float As[32 * 68];   // [kl][d]
    __shared__ float Bs[32 * 68];   // [kl][h]
    int tid = threadIdx.x;
    int ks = blockIdx.x, bm = blockIdx.y;
    int b = bm >> 3, m = bm & 7;
    int warp = tid >> 5, lane = tid & 31, gid = lane >> 2, tig = lane & 3;
    int rb = (warp & 3) * 16, vb = (warp >> 2) * 32;
    float acc[4][4] = {};

    for (int t = 0; t < 16; t++) {
        int lb = ks * 512 + t * 32;
#pragma unroll
        for (int it = 0; it < 2; it++) {
            int idx = tid + 256 * it;
            int kl = idx >> 4, d4 = (idx & 15) * 4;
            *(float4*)&As[kl * 68 + d4] =
                *(const float4*)&x[(size_t)(b * LL + lb + kl) * DD + m * 64 + d4];
            *(float4*)&Bs[kl * 68 + d4] =
                *(const float4*)&g_H1[((size_t)bm * LL + lb + kl) * 64 + d4];
        }
        __syncthreads();
#pragma unroll
        for (int kk = 0; kk < 32; kk += 8) {
            uint32_t ah[4], al[4];
            split3(As[(kk + tig) * 68 + rb + gid],         ah[0], al[0]);
            split3(As[(kk + tig) * 68 + rb + gid + 8],     ah[1], al[1]);
            split3(As[(kk + tig + 4) * 68 + rb + gid],     ah[2], al[2]);
            split3(As[(kk + tig + 4) * 68 + rb + gid + 8], ah[3], al[3]);
            uint32_t bh[4][2], bl[4][2];
#pragma unroll
            for (int ni = 0; ni < 4; ni++) {
                int cc = vb + ni * 8 + gid;
                split3(Bs[(kk + tig) * 68 + cc],     bh[ni][0], bl[ni][0]);
                split3(Bs[(kk + tig + 4) * 68 + cc], bh[ni][1], bl[ni][1]);
            }
#pragma unroll
            for (int ni = 0; ni < 4; ni++) {
                mma_tf32(acc[ni], ah, bh[ni]);
                mma_tf32(acc[ni], ah, bl[ni]);
                mma_tf32(acc[ni], al, bh[ni]);
            }
        }
        __syncthreads();
    }
    size_t base = ((size_t)(ks * 64 + bm)) * 4096;
#pragma unroll
    for (int ni = 0; ni < 4; ni++) {
        int d0 = rb + gid, h = vb + ni * 8 + tig * 2;
        float2 v0 = {acc[ni][0], acc[ni][1]};
        float2 v1 = {acc[ni][2], acc[ni][3]};
        *(float2*)&g_T1p[base + (size_t)d0 * 64 + h] = v0;
        *(float2*)&g_T1p[base + (size_t)(d0 + 8) * 64 + h] = v1;
    }
}

// ============ kernel C: T1 reduce; S = gelu(...); T2 = S fc2_2; sb = S.b2_2 ============
__global__ void __launch_bounds__(256)
sgen_kernel(const float* __restrict__ x,
            const float* __restrict__ f2w1, const float* __restrict__ f2b1,
            const float* __restrict__ f2w2, const float* __restrict__ f2b2)
{
    extern __shared__ float sm[];
    float* T1s  = sm;
    float* F1s  = T1s + 4160;
    float* F2s  = F1s + 4160;
    float* Ss   = F2s + 4160;
    float* xp   = Ss + 4160;
    float* xsums= xp + 256;
    float* b1s  = xsums + 64;
    float* b2s  = b1s + 64;
    int tid = threadIdx.x;
    int bm = blockIdx.x;
    int b = bm >> 3, m = bm & 7;

#pragma unroll
    for (int r = 0; r < 16; r++) {
        int o = tid + 256 * r;
        float s = 0.f;
#pragma unroll
        for (int ks = 0; ks < 4; ks++)
            s += g_T1p[((size_t)(ks * 64 + bm)) * 4096 + o];
        T1s[(o >> 6) * 65 + (o & 63)] = s;
    }
    {
        int d = tid & 63, p = tid >> 6;
        const float* xp0 = &x[(size_t)(b * LL + p * 512) * DD + m * 64 + d];
        float s = 0.f;
        for (int l = 0; l < 512; l++) s += xp0[(size_t)l * DD];
        xp[p * 64 + d] = s;
    }
    __syncthreads();
    if (tid < 64) xsums[tid] = xp[tid] + xp[64 + tid] + xp[128 + tid] + xp[192 + tid];

    int tx = tid & 15, ty = tid >> 4;
    float t2acc[4][4] = {};
    float sbacc[4] = {};
    for (int c = 0; c < 4; c++) {
        __syncthreads();
#pragma unroll
        for (int r = 0; r < 16; r++) {
            int i = tid + 256 * r;
            int khl = i >> 6, h = i & 63;
            F1s[khl * 65 + h] = f2w1[(size_t)m * 16384 + (c * 64 + khl) * 64 + h];
            F2s[khl * 65 + h] = f2w2[(size_t)m * 16384 + (c * 64 + khl) * 64 + h];
        }
        if (tid < 64) {
            b1s[tid] = f2b1[m * 256 + c * 64 + tid];
            b2s[tid] = f2b2[m * 256 + c * 64 + tid];
        }
        __syncthreads();
        float spre[4][4] = {};
#pragma unroll 8
        for (int h = 0; h < 64; h++) {
            float tv[4], fv[4];
#pragma unroll
            for (int ii = 0; ii < 4; ii++) tv[ii] = T1s[(ty * 4 + ii) * 65 + h];
#pragma unroll
            for (int jj = 0; jj < 4; jj++) fv[jj] = F1s[(tx * 4 + jj) * 65 + h];
#pragma unroll
            for (int ii = 0; ii < 4; ii++)
#pragma unroll
                for (int jj = 0; jj < 4; jj++)
                    spre[ii][jj] += tv[ii] * fv[jj];
        }
#pragma unroll
        for (int ii = 0; ii < 4; ii++)
#pragma unroll
            for (int jj = 0; jj < 4; jj++) {
                int d = ty * 4 + ii, khl = tx * 4 + jj;
                Ss[d * 65 + khl] = geluf(spre[ii][jj] + xsums[d] * b1s[khl]);
            }
        __syncthreads();
#pragma unroll 8
        for (int khl = 0; khl < 64; khl++) {
            float sv[4], fv[4];
#pragma unroll
            for (int ii = 0; ii < 4; ii++) sv[ii] = Ss[(ty * 4 + ii) * 65 + khl];
#pragma unroll
            for (int jj = 0; jj < 4; jj++) fv[jj] = F2s[khl * 65 + tx * 4 + jj];
#pragma unroll
            for (int ii = 0; ii < 4; ii++)
#pragma unroll
                for (int jj = 0; jj < 4; jj++)
                    t2acc[ii][jj] += sv[ii] * fv[jj];
            if (tx == 0) {
                float bv = b2s[khl];
#pragma unroll
                for (int ii = 0; ii < 4; ii++) sbacc[ii] += sv[ii] * bv;
            }
        }
    }
#pragma unroll
    for (int ii = 0; ii < 4; ii++)
#pragma unroll
        for (int jj = 0; jj < 4; jj++)
            g_T2[(size_t)bm * 4096 + (ty * 4 + ii) * 64 + tx * 4 + jj] = t2acc[ii][jj];
    if (tx == 0)
#pragma unroll
        for (int ii = 0; ii < 4; ii++) g_sb[bm * 64 + ty * 4 + ii] = sbacc[ii];
}

// ============ kernel E: mixpre = H2 @ T2^T + sb — 3xTF32 mma ============
// grid (16 ltiles, 64 bm); block 128l x 64d, K=64
__global__ void __launch_bounds__(256)
mixpre_mma()
{
    extern __shared__ float sm[];
    float* Hs  = sm;                // [128][68]
    float* Ts  = Hs + 128 * 68;     // [64][68]  [d][h]
    float* Cs  = Ts + 64 * 68;      // [64][68]
    float* sbs = Cs + 64 * 68;      // 64
    int tid = threadIdx.x;
    int l0 = blockIdx.x * 128;
    int bm = blockIdx.y;
    int b = bm >> 3, m = bm & 7;

    {
        int f4 = (tid & 15) * 4, r = tid >> 4;
#pragma unroll
        for (int it = 0; it < 8; it++) {
            int row = r + it * 16;
            *(float4*)&Hs[row * 68 + f4] =
                *(const float4*)&g_H2[((size_t)bm * LL + l0 + row) * 64 + f4];
        }
#pragma unroll
        for (int it = 0; it < 4; it++) {
            int dd = r + it * 16;
            *(float4*)&Ts[dd * 68 + f4] = *(const float4*)&g_T2[(size_t)bm * 4096 + dd * 64 + f4];
        }
        if (tid < 64) sbs[tid] = g_sb[bm * 64 + tid];
    }
    __syncthreads();

    int warp = tid >> 5, lane = tid & 31, gid = lane >> 2, tig = lane & 3;
    int mw = warp & 3, nw = warp >> 2;
    int rb = mw * 32, vb = nw * 32;

    float acc[2][4][4] = {};
#pragma unroll
    for (int kk = 0; kk < 64; kk += 8) {
        uint32_t ah[2][4], al[2][4];
#pragma unroll
        for (int mi = 0; mi < 2; mi++) {
            int rr = rb + mi * 16;
            split3(Hs[(rr + gid) * 68 + kk + tig],     ah[mi][0], al[mi][0]);
            split3(Hs[(rr + gid + 8) * 68 + kk + tig], ah[mi][1], al[mi][1]);
            split3(Hs[(rr + gid) * 68 + kk + tig + 4],     ah[mi][2], al[mi][2]);
            split3(Hs[(rr + gid + 8) * 68 + kk + tig + 4], ah[mi][3], al[mi][3]);
        }
        uint32_t bh[4][2], bl[4][2];
#pragma unroll
        for (int ni = 0; ni < 4; ni++) {
            int cc = vb + ni * 8 + gid;
            split3(Ts[cc * 68 + kk + tig],     bh[ni][0], bl[ni][0]);
            split3(Ts[cc * 68 + kk + tig + 4], bh[ni][1], bl[ni][1]);
        }
#pragma unroll
        for (int mi = 0; mi < 2; mi++)
#pragma unroll
            for (int ni = 0; ni < 4; ni++) {
                mma_tf32(acc[mi][ni], ah[mi], bh[ni]);
                mma_tf32(acc[mi][ni], ah[mi], bl[ni]);
                mma_tf32(acc[mi][ni], al[mi], bh[ni]);
            }
    }
#pragma unroll
    for (int p = 0; p < 2; p++) {
        if ((mw >> 1) == p) {
            int lr = (mw & 1) * 32;
#pragma unroll
            for (int mi = 0; mi < 2; mi++)
#pragma unroll
                for (int ni = 0; ni < 4; ni++) {
                    int rr = lr + mi * 16 + gid;
                    int cc = vb + ni * 8 + tig * 2;
                    Cs[rr * 68 + cc]           = acc[mi][ni][0] + sbs[cc];
                    Cs[rr * 68 + cc + 1]       = acc[mi][ni][1] + sbs[cc + 1];
                    Cs[(rr + 8) * 68 + cc]     = acc[mi][ni][2] + sbs[cc];
                    Cs[(rr + 8) * 68 + cc + 1] = acc[mi][ni][3] + sbs[cc + 1];
                }
        }
        __syncthreads();
#pragma unroll
        for (int it = 0; it < 4; it++) {
            int idx = tid + 256 * it;
            int row = idx >> 4, c4 = (idx & 15) * 4;
            *(float4*)&g_mixpre[(size_t)(b * LL + l0 + p * 64 + row) * DD + m * 64 + c4] =
                *(float4*)&Cs[row * 68 + c4];
        }
        __syncthreads();
    }
}

// ---------------- LN helpers ----------------
__device__ __forceinline__ float blk_sum128(float v, float* sbuf)
{
#pragma unroll
    for (int o = 16; o; o >>= 1) v += __shfl_xor_sync(0xffffffffu, v, o);
    __syncthreads();
    if ((threadIdx.x & 31) == 0) sbuf[threadIdx.x >> 5] = v;
    __syncthreads();
    return sbuf[0] + sbuf[1] + sbuf[2] + sbuf[3];
}

__global__ void __launch_bounds__(128)
ln_mix_kernel(const float* __restrict__ g1, const float* __restrict__ b1,
              const float* __restrict__ g2, const float* __restrict__ b2)
{
    __shared__ float sbuf[4];
    size_t row = blockIdx.x;
    int t = threadIdx.x;
    const float* r = g_mixpre + row * DD;
    float v[4];
#pragma unroll
    for (int i = 0; i < 4; i++) v[i] = r[t + 128 * i];
    float mean = blk_sum128(v[0] + v[1] + v[2] + v[3], sbuf) * (1.0f / 512.0f);
    float sq = 0.f;
#pragma unroll
    for (int i = 0; i < 4; i++) { float d = v[i] - mean; sq += d * d; }
    float var = blk_sum128(sq, sbuf) * (1.0f / 512.0f);
    float inv = rsqrtf(var + 1e-5f);
    float mx[4];
#pragma unroll
    for (int i = 0; i < 4; i++) {
        int c = t + 128 * i;
        mx[i] = (v[i] - mean) * inv * g1[c] + b1[c];
        g_mix[row * DD + c] = mx[i];
    }
    float mean2 = blk_sum128(mx[0] + mx[1] + mx[2] + mx[3], sbuf) * (1.0f / 512.0f);
    float sq2 = 0.f;
#pragma unroll
    for (int i = 0; i < 4; i++) { float d = mx[i] - mean2; sq2 += d * d; }
    float var2 = blk_sum128(sq2, sbuf) * (1.0f / 512.0f);
    float inv2 = rsqrtf(var2 + 1e-5f);
#pragma unroll
    for (int i = 0; i < 4; i++) {
        int c = t + 128 * i;
        g_u[row * DD + c] = (mx[i] - mean2) * inv2 * g2[c] + b2[c];
    }
}

// ============ bottleneck 1x1 + GLU via tf32 mma ============
__global__ void __launch_bounds__(256)
bneck_glu_mma(const float* __restrict__ bw, const float* __restrict__ bb)
{
    __shared__ float As[16][132];
    __shared__ float Bs[16][132];
    __shared__ float Cs[32][68];
    int tid = threadIdx.x;
    int warp = tid >> 5, lane = tid & 31;
    int mw = warp & 3, nw = warp >> 2;
    int gid = lane >> 2, tig = lane & 3;
    int r0 = blockIdx.y * 128, n0 = blockIdx.x * 64;

    float acc[2][8][4];
#pragma unroll
    for (int mi = 0; mi < 2; mi++)
#pragma unroll
        for (int ni = 0; ni < 8; ni++)
#pragma unroll
            for (int q = 0; q < 4; q++) acc[mi][ni][q] = 0.f;

    int arow = tid >> 1;
    int akq  = (tid & 1) * 8;
    int vcol = tid >> 1;
    int brr  = (vcol & 1) ? (512 + n0 + (vcol >> 1)) : (n0 + (vcol >> 1));

    for (int k0 = 0; k0 < 512; k0 += 16) {
        {
            const float* p = &g_u[(size_t)(r0 + arow) * 512 + k0 + akq];
            float4 v0 = *(const float4*)p;
            float4 v1 = *(const float4*)(p + 4);
            As[akq + 0][arow] = tf32r(v0.x); As[akq + 1][arow] = tf32r(v0.y);
            As[akq + 2][arow] = tf32r(v0.z); As[akq + 3][arow] = tf32r(v0.w);
            As[akq + 4][arow] = tf32r(v1.x); As[akq + 5][arow] = tf32r(v1.y);
            As[akq + 6][arow] = tf32r(v1.z); As[akq + 7][arow] = tf32r(v1.w);
        }
        {
            const float* p = &bw[(size_t)brr * 512 + k0 + akq];
            float4 v0 = *(const float4*)p;
            float4 v1 = *(const float4*)(p + 4);
            Bs[akq + 0][vcol] = tf32r(v0.x); Bs[akq + 1][vcol] = tf32r(v0.y);
            Bs[akq + 2][vcol] = tf32r(v0.z); Bs[akq + 3][vcol] = tf32r(v0.w);
            Bs[akq + 4][vcol] = tf32r(v1.x); Bs[akq + 5][vcol] = tf32r(v1.y);
            Bs[akq + 6][vcol] = tf32r(v1.z); Bs[akq + 7][vcol] = tf32r(v1.w);
        }
        __syncthreads();
#pragma unroll
        for (int kk = 0; kk < 16; kk += 8) {
            uint32_t a[2][4];
#pragma unroll
            for (int mi = 0; mi < 2; mi++) {
                int rb = mw * 32 + mi * 16;
                a[mi][0] = __float_as_uint(As[kk + tig][rb + gid]);
                a[mi][1] = __float_as_uint(As[kk + tig][rb + gid + 8]);
                a[mi][2] = __float_as_uint(As[kk + tig + 4][rb + gid]);
                a[mi][3] = __float_as_uint(As[kk + tig + 4][rb + gid + 8]);
            }
            uint32_t bfr[8][2];
#pragma unroll
            for (int ni = 0; ni < 8; ni++) {
                int vb = nw * 64 + ni * 8;
                bfr[ni][0] = __float_as_uint(Bs[kk + tig][vb + gid]);
                bfr[ni][1] = __float_as_uint(Bs[kk + tig + 4][vb + gid]);
            }
#pragma unroll
            for (int mi = 0; mi < 2; mi++)
#pragma unroll
                for (int ni = 0; ni < 8; ni++)
                    mma_tf32(acc[mi][ni], a[mi], bfr[ni]);
        }
        __syncthreads();
    }

    float bbA[8], bbB[8];
#pragma unroll
    for (int ni = 0; ni < 8; ni++) {
        int cR = n0 + nw * 32 + ni * 4 + tig;
        bbA[ni] = bb[cR];
        bbB[ni] = bb[512 + cR];
    }
    for (int p = 0; p < 4; p++) {
        if (mw == p) {
#pragma unroll
            for (int mi = 0; mi < 2; mi++)
#pragma unroll
                for (int ni = 0; ni < 8; ni++) {
                    int cc = nw * 32 + ni * 4 + tig;
                    float ga0 = acc[mi][ni][0] + bbA[ni];
                    float gb0 = acc[mi][ni][1] + bbB[ni];
                    float ga1 = acc[mi][ni][2] + bbA[ni];
                    float gb1 = acc[mi][ni][3] + bbB[ni];
                    Cs[mi * 16 + gid][cc]     = ga0 * sigmoidf_(gb0);
                    Cs[mi * 16 + gid + 8][cc] = ga1 * sigmoidf_(gb1);
                }
        }
        __syncthreads();
        {
            int row = tid >> 3, c = (tid & 7) * 8;
            float4 v0 = *(float4*)&Cs[row][c];
            float4 v1 = *(float4*)&Cs[row][c + 4];
            float* op = &g_c0[(size_t)(r0 + p * 32 + row) * 512 + n0 + c];
            *(float4*)op = v0;
            *(float4*)(op + 4) = v1;
        }
        __syncthreads();
    }
}

// ============ depthwise conv (K=31, pad 15) — register sliding window ============
__global__ void __launch_bounds__(256)
dwconv_kernel(const float* __restrict__ dw, const float* __restrict__ dwb)
{
    __shared__ float ins[158 * 64];
    __shared__ float wts[64 * 31];
    __shared__ float bs[64];
    int tid = threadIdx.x;
    int c0 = blockIdx.x * 64;
    int l0 = blockIdx.y * 128;
    int b  = blockIdx.z;
    for (int i = tid; i < 158 * 64; i += 256) {
        int rr = i >> 6, c = i & 63;
        int l = l0 - 15 + rr;
        ins[i] = (l >= 0 && l < LL) ? g_c0[((size_t)(b * LL + l)) * DD + c0 + c] : 0.f;
    }
    for (int i = tid; i < 64 * 31; i += 256)
        wts[i] = dw[c0 * 31 + i];
    if (tid < 64) bs[tid] = dwb[c0 + tid];
    __syncthreads();
    int tx = tid & 63, ty = tid >> 6;
    float w[31];
#pragma unroll
    for (int j = 0; j < 31; j++) w[j] = wts[tx * 31 + j];
    float bias = bs[tx];
    int base = ty * 32;
    float win[31];
#pragma unroll
    for (int j = 0; j < 30; j++) win[j] = ins[(base + j) * 64 + tx];
#pragma unroll
    for (int li = 0; li < 32; li++) {
        win[30] = ins[(base + li + 30) * 64 + tx];
        float acc = bias;
#pragma unroll
        for (int j = 0; j < 31; j++) acc += win[j] * w[j];
        g_v[((size_t)(b * LL + l0 + base + li)) * DD + c0 + tx] = acc;
#pragma unroll
        for (int j = 0; j < 30; j++) win[j] = win[j + 1];
    }
}

// ============ LN2 + gelu ============
__global__ void __launch_bounds__(128)
ln2_gelu_kernel(const float* __restrict__ g2, const float* __restrict__ b2)
{
    __shared__ float sbuf[4];
    size_t row = blockIdx.x;
    int t = threadIdx.x;
    const float* r = g_v + row * DD;
    float v[4];
#pragma unroll
    for (int i = 0; i < 4; i++) v[i] = r[t + 128 * i];
    float mean = blk_sum128(v[0] + v[1] + v[2] + v[3], sbuf) * (1.0f / 512.0f);
    float sq = 0.f;
#pragma unroll
    for (int i = 0; i < 4; i++) { float d = v[i] - mean; sq += d * d; }
    float var = blk_sum128(sq, sbuf) * (1.0f / 512.0f);
    float inv = rsqrtf(var + 1e-5f);
#pragma unroll
    for (int i = 0; i < 4; i++) {
        int c = t + 128 * i;
        g_w[row * DD + c] = geluf((v[i] - mean) * inv * g2[c] + b2[c]);
    }
}

// ============ final linear + bias + residual via tf32 mma ============
__global__ void __launch_bounds__(256)
linear_res_mma(const float* __restrict__ lw, const float* __restrict__ lb,
               float* __restrict__ out)
{
    __shared__ float As[16][132];
    __shared__ float Bs[16][132];
    __shared__ float Cs[32][132];
    int tid = threadIdx.x;
    int warp = tid >> 5, lane = tid & 31;
    int mw = warp & 3, nw = warp >> 2;
    int gid = lane >> 2, tig = lane & 3;
    int r0 = blockIdx.y * 128, n0 = blockIdx.x * 128;

    float acc[2][8][4];
#pragma unroll
    for (int mi = 0; mi < 2; mi++)
#pragma unroll
        for (int ni = 0; ni < 8; ni++)
#pragma unroll
            for (int q = 0; q < 4; q++) acc[mi][ni][q] = 0.f;

    int arow = tid >> 1;
    int akq  = (tid & 1) * 8;

    for (int k0 = 0; k0 < 512; k0 += 16) {
        {
            const float* p = &g_w[(size_t)(r0 + arow) * 512 + k0 + akq];
            float4 v0 = *(const float4*)p;
            float4 v1 = *(const float4*)(p + 4);
            As[akq + 0][arow] = tf32r(v0.x); As[akq + 1][arow] = tf32r(v0.y);
            As[akq + 2][arow] = tf32r(v0.z); As[akq + 3][arow] = tf32r(v0.w);
            As[akq + 4][arow] = tf32r(v1.x); As[akq + 5][arow] = tf32r(v1.y);
            As[akq + 6][arow] = tf32r(v1.z); As[akq + 7][arow] = tf32r(v1.w);
        }
        {
            const float* p = &lw[(size_t)(n0 + arow) * 512 + k0 + akq];
            float4 v0 = *(const float4*)p;
            float4 v1 = *(const float4*)(p + 4);
            Bs[akq + 0][arow] = tf32r(v0.x); Bs[akq + 1][arow] = tf32r(v0.y);
            Bs[akq + 2][arow] = tf32r(v0.z); Bs[akq + 3][arow] = tf32r(v0.w);
            Bs[akq + 4][arow] = tf32r(v1.x); Bs[akq + 5][arow] = tf32r(v1.y);
            Bs[akq + 6][arow] = tf32r(v1.z); Bs[akq + 7][arow] = tf32r(v1.w);
        }
        __syncthreads();
#pragma unroll
        for (int kk = 0; kk < 16; kk += 8) {
            uint32_t a[2][4];
#pragma unroll
            for (int mi = 0; mi < 2; mi++) {
                int rb = mw * 32 + mi * 16;
                a[mi][0] = __float_as_uint(As[kk + tig][rb + gid]);
                a[mi][1] = __float_as_uint(As[kk + tig][rb + gid + 8]);
                a[mi][2] = __float_as_uint(As[kk + tig + 4][rb + gid]);
                a[mi][3] = __float_as_uint(As[kk + tig + 4][rb + gid + 8]);
            }
            uint32_t bfr[8][2];
#pragma unroll
            for (int ni = 0; ni < 8; ni++) {
                int vb = nw * 64 + ni * 8;
                bfr[ni][0] = __float_as_uint(Bs[kk + tig][vb + gid]);
                bfr[ni][1] = __float_as_uint(Bs[kk + tig + 4][vb + gid]);
            }
#pragma unroll
            for (int mi = 0; mi < 2; mi++)
#pragma unroll
                for (int ni = 0; ni < 8; ni++)
                    mma_tf32(acc[mi][ni], a[mi], bfr[ni]);
        }
        __syncthreads();
    }

    for (int p = 0; p < 4; p++) {
        if (mw == p) {
#pragma unroll
            for (int mi = 0; mi < 2; mi++)
#pragma unroll
                for (int ni = 0; ni < 8; ni++) {
                    int cc = nw * 64 + ni * 8 + tig * 2;
                    Cs[mi * 16 + gid][cc]         = acc[mi][ni][0];
                    Cs[mi * 16 + gid][cc + 1]     = acc[mi][ni][1];
                    Cs[mi * 16 + gid + 8][cc]     = acc[mi][ni][2];
                    Cs[mi * 16 + gid + 8][cc + 1] = acc[mi][ni][3];
                }
        }
        __syncthreads();
        {
            int row = tid >> 3, c0c = (tid & 7) * 16;
            size_t gro = (size_t)(r0 + p * 32 + row) * 512 + n0;
#pragma unroll
            for (int q = 0; q < 4; q++) {
                int c = c0c + q * 4;
                float4 v = *(float4*)&Cs[row][c];
                float4 mres = *(const float4*)&g_mix[gro + c];
                float4 bl = *(const float4*)&lb[n0 + c];
                v.x += bl.x + mres.x; v.y += bl.y + mres.y;
                v.z += bl.z + mres.z; v.w += bl.w + mres.w;
                *(float4*)&out[gro + c] = v;
            }
        }
        __syncthreads();
    }
}

// ---------------- launch ----------------
extern "C" void kernel_launch(void* const* d_in, const int* in_sizes, int n_in,
                              void* d_out, int out_size)
{
    (void)in_sizes; (void)n_in; (void)out_size;
    const float* x      = (const float*)d_in[0];
    const float* w1f1w  = (const float*)d_in[1];
    const float* w1f1b  = (const float*)d_in[2];
    const float* w1f2w  = (const float*)d_in[3];
    const float* w1f2b  = (const float*)d_in[4];
    const float* w2f1w  = (const float*)d_in[5];
    const float* w2f1b  = (const float*)d_in[6];
    const float* w2f2w  = (const float*)d_in[7];
    const float* w2f2b  = (const float*)d_in[8];
    const float* lnmg   = (const float*)d_in[9];
    const float* lnmb   = (const float*)d_in[10];
    const float* c1g    = (const float*)d_in[11];
    const float* c1b    = (const float*)d_in[12];
    const float* bw     = (const float*)d_in[13];
    const float* bb     = (const float*)d_in[14];
    const float* dww    = (const float*)d_in[15];
    const float* dwb    = (const float*)d_in[16];
    const float* c2g    = (const float*)d_in[17];
    const float* c2b    = (const float*)d_in[18];
    const float* lw     = (const float*)d_in[19];
    const float* lb     = (const float*)d_in[20];
    float* out = (float*)d_out;

    const int SGEN_SMEM = (4 * 4160 + 256 + 64 + 64 + 64) * 4;
    const int FC1_SMEM  = (128 * 68 + 64 * 68 * 3 + 128) * 4;      // 87,552 B
    const int MIX_SMEM  = (128 * 68 + 64 * 68 * 2 + 64) * 4;       // 69,888 B
    cudaFuncSetAttribute(sgen_kernel, cudaFuncAttributeMaxDynamicSharedMemorySize, SGEN_SMEM);
    cudaFuncSetAttribute(fc1_mma, cudaFuncAttributeMaxDynamicSharedMemorySize, FC1_SMEM);
    cudaFuncSetAttribute(mixpre_mma, cudaFuncAttributeMaxDynamicSharedMemorySize, MIX_SMEM);

    fc1_mma<<<dim3(16, 64), 256, FC1_SMEM>>>(x, w1f1w, w1f1b, w2f1w, w2f1b);
    t1_mma<<<dim3(4, 64), 256>>>(x);
    sgen_kernel<<<64, 256, SGEN_SMEM>>>(x, w1f2w, w1f2b, w2f2w, w2f2b);
    mixpre_mma<<<dim3(16, 64), 256, MIX_SMEM>>>();
    ln_mix_kernel<<<BB * LL, 128>>>(lnmg, lnmb, c1g, c1b);
    bneck_glu_mma<<<dim3(8, 128), 256>>>(bw, bb);
    dwconv_kernel<<<dim3(8, 16, 8), 256>>>(dww, dwb);
    ln2_gelu_kernel<<<BB * LL, 128>>>(c2g, c2b);
    linear_res_mma<<<dim3(4, 128), 256>>>(lw, lb, out);
}

// round 7
// speedup vs baseline: 2.9859x; 1.0087x over previous
#include <cuda_runtime.h>
#include <math.h>
#include <stdint.h>

#define BB 8
#define LL 2048
#define DD 512
#define MM 8
#define DHH 64
#define KHH 256

// ---------------- scratch (device globals; no allocations) ----------------
__device__ float g_H1[64 * 2048 * 64];
__device__ float g_H2[64 * 2048 * 64];
__device__ float g_T1p[4 * 64 * 64 * 64];
__device__ float g_T2[64 * 64 * 64];
__device__ float g_sb[64 * 64];
__device__ float g_mixpre[BB * LL * DD];
__device__ float g_mix[BB * LL * DD];
__device__ float g_u[BB * LL * DD];
__device__ float g_c0[BB * LL * DD];
__device__ float g_v[BB * LL * DD];
__device__ float g_w[BB * LL * DD];

__device__ __forceinline__ float geluf(float x) {
    return 0.5f * x * (1.0f + erff(x * 0.7071067811865476f));
}
__device__ __forceinline__ float sigmoidf_(float x) {
    return 1.0f / (1.0f + expf(-x));
}
__device__ __forceinline__ float pe_val(int l, int c) {
    float ang = (float)l * expf(-(float)(c & ~1) * 0.0179889460390160f);
    return (c & 1) ? cosf(ang) : sinf(ang);
}
__device__ __forceinline__ float tf32r(float x) {
    uint32_t r;
    asm("cvt.rna.tf32.f32 %0, %1;" : "=r"(r) : "f"(x));
    return __uint_as_float(r);
}
__device__ __forceinline__ void split3(float v, uint32_t& hi, uint32_t& lo) {
    uint32_t h;
    asm("cvt.rna.tf32.f32 %0, %1;" : "=r"(h) : "f"(v));
    float r = v - __uint_as_float(h);
    uint32_t l;
    asm("cvt.rna.tf32.f32 %0, %1;" : "=r"(l) : "f"(r));
    hi = h; lo = l;
}
__device__ __forceinline__ void mma_tf32(float* c, const uint32_t* a, const uint32_t* b)
{
    asm volatile(
        "mma.sync.aligned.m16n8k8.row.col.f32.tf32.tf32.f32 "
        "{%0,%1,%2,%3}, {%4,%5,%6,%7}, {%8,%9}, {%0,%1,%2,%3};\n"
        : "+f"(c[0]), "+f"(c[1]), "+f"(c[2]), "+f"(c[3])
        : "r"(a[0]), "r"(a[1]), "r"(a[2]), "r"(a[3]), "r"(b[0]), "r"(b[1]));
}

// ============ kernel A: H1,H2 = gelu(fc1_{1,2}(x + pe)) — 3xTF32 mma ============
__global__ void __launch_bounds__(256)
fc1_mma(const float* __restrict__ x,
        const float* __restrict__ f1w_1, const float* __restrict__ f1b_1,
        const float* __restrict__ f1w_2, const float* __restrict__ f1b_2)
{
    extern __shared__ float sm[];
    float* Xs  = sm;                 // [128][68]
    float* W1s = Xs + 128 * 68;      // [64][68]  [h][f]
    float* W2s = W1s + 64 * 68;      // [64][68]
    float* Cs  = W2s + 64 * 68;      // [64][68]
    float* b1s = Cs + 64 * 68;       // 64
    float* b2s = b1s + 64;           // 64
    int tid = threadIdx.x;
    int l0 = blockIdx.x * 128;
    int bm = blockIdx.y;
    int b = bm >> 3, m = bm & 7;

    {
        int f4 = (tid & 15) * 4, r = tid >> 4;
#pragma unroll
        for (int it = 0; it < 8; it++) {
            int row = r + it * 16;
            int l = l0 + row;
            float4 v = *(const float4*)&x[(size_t)(b * LL + l) * DD + m * 64 + f4];
            Xs[row * 68 + f4 + 0] = v.x + pe_val(l, m * 64 + f4 + 0);
            Xs[row * 68 + f4 + 1] = v.y + pe_val(l, m * 64 + f4 + 1);
            Xs[row * 68 + f4 + 2] = v.z + pe_val(l, m * 64 + f4 + 2);
            Xs[row * 68 + f4 + 3] = v.w + pe_val(l, m * 64 + f4 + 3);
        }
#pragma unroll
        for (int it = 0; it < 4; it++) {
            int hh = r + it * 16;
            *(float4*)&W1s[hh * 68 + f4] = *(const float4*)&f1w_1[m * 4096 + hh * 64 + f4];
            *(float4*)&W2s[hh * 68 + f4] = *(const float4*)&f1w_2[m * 4096 + hh * 64 + f4];
        }
        if (tid < 64) { b1s[tid] = f1b_1[m * 64 + tid]; b2s[tid] = f1b_2[m * 64 + tid]; }
    }
    __syncthreads();

    int warp = tid >> 5, lane = tid & 31, gid = lane >> 2, tig = lane & 3;
    int mw = warp & 3, nw = warp >> 2;
    int rb = mw * 32, vb = nw * 32;

    for (int which = 0; which < 2; which++) {
        const float* Ws = which ? W2s : W1s;
        const float* bs = which ? b2s : b1s;
        float* H = which ? g_H2 : g_H1;
        float acc[2][4][4] = {};
#pragma unroll
        for (int kk = 0; kk < 64; kk += 8) {
            uint32_t ah[2][4], al[2][4];
#pragma unroll
            for (int mi = 0; mi < 2; mi++) {
                int rr = rb + mi * 16;
                split3(Xs[(rr + gid) * 68 + kk + tig],     ah[mi][0], al[mi][0]);
                split3(Xs[(rr + gid + 8) * 68 + kk + tig], ah[mi][1], al[mi][1]);
                split3(Xs[(rr + gid) * 68 + kk + tig + 4],     ah[mi][2], al[mi][2]);
                split3(Xs[(rr + gid + 8) * 68 + kk + tig + 4], ah[mi][3], al[mi][3]);
            }
            uint32_t bh[4][2], bl[4][2];
#pragma unroll
            for (int ni = 0; ni < 4; ni++) {
                int cc = vb + ni * 8 + gid;
                split3(Ws[cc * 68 + kk + tig],     bh[ni][0], bl[ni][0]);
                split3(Ws[cc * 68 + kk + tig + 4], bh[ni][1], bl[ni][1]);
            }
#pragma unroll
            for (int mi = 0; mi < 2; mi++)
#pragma unroll
                for (int ni = 0; ni < 4; ni++) {
                    mma_tf32(acc[mi][ni], ah[mi], bh[ni]);
                    mma_tf32(acc[mi][ni], ah[mi], bl[ni]);
                    mma_tf32(acc[mi][ni], al[mi], bh[ni]);
                }
        }
#pragma unroll
        for (int p = 0; p < 2; p++) {
            if ((mw >> 1) == p) {
                int lr = (mw & 1) * 32;
#pragma unroll
                for (int mi = 0; mi < 2; mi++)
#pragma unroll
                    for (int ni = 0; ni < 4; ni++) {
                        int rr = lr + mi * 16 + gid;
                        int cc = vb + ni * 8 + tig * 2;
                        Cs[rr * 68 + cc]           = geluf(acc[mi][ni][0] + bs[cc]);
                        Cs[rr * 68 + cc + 1]       = geluf(acc[mi][ni][1] + bs[cc + 1]);
                        Cs[(rr + 8) * 68 + cc]     = geluf(acc[mi][ni][2] + bs[cc]);
                        Cs[(rr + 8) * 68 + cc + 1] = geluf(acc[mi][ni][3] + bs[cc + 1]);
                    }
            }
            __syncthreads();
#pragma unroll
            for (int it = 0; it < 4; it++) {
                int idx = tid + 256 * it;
                int row = idx >> 4, c4 = (idx & 15) * 4;
                *(float4*)&H[((size_t)bm * LL + l0 + p * 64 + row) * 64 + c4] =
                    *(float4*)&Cs[row * 68 + c4];
            }
            __syncthreads();
        }
    }
}

// ============ kernel B: T1 partial = X_head^T @ H1 — 3xTF32 mma, double-buffered ============
// grid (4 ks, 64 bm); out [64d x 64h], K=512 per block
__global__ void __launch_bounds__(256)
t1_mma(const float* __restrict__ x)
{
    __shared__ float As[2][32][68];   // [buf][kl][d]
    __shared__ float Bs[2][32][68];   // [buf][kl][h]
    int tid = threadIdx.x;
    int ks = blockIdx.x, bm = blockIdx.y;
    int b = bm >> 3, m = bm & 7;
    int warp = tid >> 5, lane = tid & 31, gid = lane >> 2, tig = lane & 3;
    int rb = (warp & 3) * 16, vb = (warp >> 2) * 32;
    float acc[4][4] = {};

    int kl0 = tid >> 4,          d40 = (tid & 15) * 4;
    int kl1 = (tid + 256) >> 4,  d41 = (tid & 15) * 4;
    int lb0 = ks * 512;

    float4 xa0, xa1, hb0, hb1;
    xa0 = *(const float4*)&x[(size_t)(b * LL + lb0 + kl0) * DD + m * 64 + d40];
    xa1 = *(const float4*)&x[(size_t)(b * LL + lb0 + kl1) * DD + m * 64 + d41];
    hb0 = *(const float4*)&g_H1[((size_t)bm * LL + lb0 + kl0) * 64 + d40];
    hb1 = *(const float4*)&g_H1[((size_t)bm * LL + lb0 + kl1) * 64 + d41];
    *(float4*)&As[0][kl0][d40] = xa0;
    *(float4*)&As[0][kl1][d41] = xa1;
    *(float4*)&Bs[0][kl0][d40] = hb0;
    *(float4*)&Bs[0][kl1][d41] = hb1;
    __syncthreads();

    for (int t = 0; t < 16; t++) {
        int cur = t & 1;
        if (t < 15) {
            int lb = ks * 512 + (t + 1) * 32;
            xa0 = *(const float4*)&x[(size_t)(b * LL + lb + kl0) * DD + m * 64 + d40];
            xa1 = *(const float4*)&x[(size_t)(b * LL + lb + kl1) * DD + m * 64 + d41];
            hb0 = *(const float4*)&g_H1[((size_t)bm * LL + lb + kl0) * 64 + d40];
            hb1 = *(const float4*)&g_H1[((size_t)bm * LL + lb + kl1) * 64 + d41];
        }
#pragma unroll
        for (int kk = 0; kk < 32; kk += 8) {
            uint32_t ah[4], al[4];
            split3(As[cur][kk + tig][rb + gid],         ah[0], al[0]);
            split3(As[cur][kk + tig][rb + gid + 8],     ah[1], al[1]);
            split3(As[cur][kk + tig + 4][rb + gid],     ah[2], al[2]);
            split3(As[cur][kk + tig + 4][rb + gid + 8], ah[3], al[3]);
            uint32_t bh[4][2], bl[4][2];
#pragma unroll
            for (int ni = 0; ni < 4; ni++) {
                int cc = vb + ni * 8 + gid;
                split3(Bs[cur][kk + tig][cc],     bh[ni][0], bl[ni][0]);
                split3(Bs[cur][kk + tig + 4][cc], bh[ni][1], bl[ni][1]);
            }
#pragma unroll
            for (int ni = 0; ni < 4; ni++) {
                mma_tf32(acc[ni], ah, bh[ni]);
                mma_tf32(acc[ni], ah, bl[ni]);
                mma_tf32(acc[ni], al, bh[ni]);
            }
        }
        if (t < 15) {
            *(float4*)&As[cur ^ 1][kl0][d40] = xa0;
            *(float4*)&As[cur ^ 1][kl1][d41] = xa1;
            *(float4*)&Bs[cur ^ 1][kl0][d40] = hb0;
            *(float4*)&Bs[cur ^ 1][kl1][d41] = hb1;
        }
        __syncthreads();
    }
    size_t base = ((size_t)(ks * 64 + bm)) * 4096;
#pragma unroll
    for (int ni = 0; ni < 4; ni++) {
        int d0 = rb + gid, h = vb + ni * 8 + tig * 2;
        float2 v0 = {acc[ni][0], acc[ni][1]};
        float2 v1 = {acc[ni][2], acc[ni][3]};
        *(float2*)&g_T1p[base + (size_t)d0 * 64 + h] = v0;
        *(float2*)&g_T1p[base + (size_t)(d0 + 8) * 64 + h] = v1;
    }
}

// ============ kernel C: T1 reduce; S = gelu(...); T2 = S fc2_2; sb = S.b2_2 ============
__global__ void __launch_bounds__(256)
sgen_kernel(const float* __restrict__ x,
            const float* __restrict__ f2w1, const float* __restrict__ f2b1,
            const float* __restrict__ f2w2, const float* __restrict__ f2b2)
{
    extern __shared__ float sm[];
    float* T1s  = sm;
    float* F1s  = T1s + 4160;
    float* F2s  = F1s + 4160;
    float* Ss   = F2s + 4160;
    float* xp   = Ss + 4160;
    float* xsums= xp + 256;
    float* b1s  = xsums + 64;
    float* b2s  = b1s + 64;
    int tid = threadIdx.x;
    int bm = blockIdx.x;
    int b = bm >> 3, m = bm & 7;

#pragma unroll
    for (int r = 0; r < 16; r++) {
        int o = tid + 256 * r;
        float s = 0.f;
#pragma unroll
        for (int ks = 0; ks < 4; ks++)
            s += g_T1p[((size_t)(ks * 64 + bm)) * 4096 + o];
        T1s[(o >> 6) * 65 + (o & 63)] = s;
    }
    {
        int d = tid & 63, p = tid >> 6;
        const float* xp0 = &x[(size_t)(b * LL + p * 512) * DD + m * 64 + d];
        float s = 0.f;
        for (int l = 0; l < 512; l++) s += xp0[(size_t)l * DD];
        xp[p * 64 + d] = s;
    }
    __syncthreads();
    if (tid < 64) xsums[tid] = xp[tid] + xp[64 + tid] + xp[128 + tid] + xp[192 + tid];

    int tx = tid & 15, ty = tid >> 4;
    float t2acc[4][4] = {};
    float sbacc[4] = {};
    for (int c = 0; c < 4; c++) {
        __syncthreads();
#pragma unroll
        for (int r = 0; r < 16; r++) {
            int i = tid + 256 * r;
            int khl = i >> 6, h = i & 63;
            F1s[khl * 65 + h] = f2w1[(size_t)m * 16384 + (c * 64 + khl) * 64 + h];
            F2s[khl * 65 + h] = f2w2[(size_t)m * 16384 + (c * 64 + khl) * 64 + h];
        }
        if (tid < 64) {
            b1s[tid] = f2b1[m * 256 + c * 64 + tid];
            b2s[tid] = f2b2[m * 256 + c * 64 + tid];
        }
        __syncthreads();
        float spre[4][4] = {};
#pragma unroll 8
        for (int h = 0; h < 64; h++) {
            float tv[4], fv[4];
#pragma unroll
            for (int ii = 0; ii < 4; ii++) tv[ii] = T1s[(ty * 4 + ii) * 65 + h];
#pragma unroll
            for (int jj = 0; jj < 4; jj++) fv[jj] = F1s[(tx * 4 + jj) * 65 + h];
#pragma unroll
            for (int ii = 0; ii < 4; ii++)
#pragma unroll
                for (int jj = 0; jj < 4; jj++)
                    spre[ii][jj] += tv[ii] * fv[jj];
        }
#pragma unroll
        for (int ii = 0; ii < 4; ii++)
#pragma unroll
            for (int jj = 0; jj < 4; jj++) {
                int d = ty * 4 + ii, khl = tx * 4 + jj;
                Ss[d * 65 + khl] = geluf(spre[ii][jj] + xsums[d] * b1s[khl]);
            }
        __syncthreads();
#pragma unroll 8
        for (int khl = 0; khl < 64; khl++) {
            float sv[4], fv[4];
#pragma unroll
            for (int ii = 0; ii < 4; ii++) sv[ii] = Ss[(ty * 4 + ii) * 65 + khl];
#pragma unroll
            for (int jj = 0; jj < 4; jj++) fv[jj] = F2s[khl * 65 + tx * 4 + jj];
#pragma unroll
            for (int ii = 0; ii < 4; ii++)
#pragma unroll
                for (int jj = 0; jj < 4; jj++)
                    t2acc[ii][jj] += sv[ii] * fv[jj];
            if (tx == 0) {
                float bv = b2s[khl];
#pragma unroll
                for (int ii = 0; ii < 4; ii++) sbacc[ii] += sv[ii] * bv;
            }
        }
    }
#pragma unroll
    for (int ii = 0; ii < 4; ii++)
#pragma unroll
        for (int jj = 0; jj < 4; jj++)
            g_T2[(size_t)bm * 4096 + (ty * 4 + ii) * 64 + tx * 4 + jj] = t2acc[ii][jj];
    if (tx == 0)
#pragma unroll
        for (int ii = 0; ii < 4; ii++) g_sb[bm * 64 + ty * 4 + ii] = sbacc[ii];
}

// ============ kernel E: mixpre = H2 @ T2^T + sb — 3xTF32 mma ============
__global__ void __launch_bounds__(256)
mixpre_mma()
{
    extern __shared__ float sm[];
    float* Hs  = sm;                // [128][68]
    float* Ts  = Hs + 128 * 68;     // [64][68]  [d][h]
    float* Cs  = Ts + 64 * 68;      // [64][68]
    float* sbs = Cs + 64 * 68;      // 64
    int tid = threadIdx.x;
    int l0 = blockIdx.x * 128;
    int bm = blockIdx.y;
    int b = bm >> 3, m = bm & 7;

    {
        int f4 = (tid & 15) * 4, r = tid >> 4;
#pragma unroll
        for (int it = 0; it < 8; it++) {
            int row = r + it * 16;
            *(float4*)&Hs[row * 68 + f4] =
                *(const float4*)&g_H2[((size_t)bm * LL + l0 + row) * 64 + f4];
        }
#pragma unroll
        for (int it = 0; it < 4; it++) {
            int dd = r + it * 16;
            *(float4*)&Ts[dd * 68 + f4] = *(const float4*)&g_T2[(size_t)bm * 4096 + dd * 64 + f4];
        }
        if (tid < 64) sbs[tid] = g_sb[bm * 64 + tid];
    }
    __syncthreads();

    int warp = tid >> 5, lane = tid & 31, gid = lane >> 2, tig = lane & 3;
    int mw = warp & 3, nw = warp >> 2;
    int rb = mw * 32, vb = nw * 32;

    float acc[2][4][4] = {};
#pragma unroll
    for (int kk = 0; kk < 64; kk += 8) {
        uint32_t ah[2][4], al[2][4];
#pragma unroll
        for (int mi = 0; mi < 2; mi++) {
            int rr = rb + mi * 16;
            split3(Hs[(rr + gid) * 68 + kk + tig],     ah[mi][0], al[mi][0]);
            split3(Hs[(rr + gid + 8) * 68 + kk + tig], ah[mi][1], al[mi][1]);
            split3(Hs[(rr + gid) * 68 + kk + tig + 4],     ah[mi][2], al[mi][2]);
            split3(Hs[(rr + gid + 8) * 68 + kk + tig + 4], ah[mi][3], al[mi][3]);
        }
        uint32_t bh[4][2], bl[4][2];
#pragma unroll
        for (int ni = 0; ni < 4; ni++) {
            int cc = vb + ni * 8 + gid;
            split3(Ts[cc * 68 + kk + tig],     bh[ni][0], bl[ni][0]);
            split3(Ts[cc * 68 + kk + tig + 4], bh[ni][1], bl[ni][1]);
        }
#pragma unroll
        for (int mi = 0; mi < 2; mi++)
#pragma unroll
            for (int ni = 0; ni < 4; ni++) {
                mma_tf32(acc[mi][ni], ah[mi], bh[ni]);
                mma_tf32(acc[mi][ni], ah[mi], bl[ni]);
                mma_tf32(acc[mi][ni], al[mi], bh[ni]);
            }
    }
#pragma unroll
    for (int p = 0; p < 2; p++) {
        if ((mw >> 1) == p) {
            int lr = (mw & 1) * 32;
#pragma unroll
            for (int mi = 0; mi < 2; mi++)
#pragma unroll
                for (int ni = 0; ni < 4; ni++) {
                    int rr = lr + mi * 16 + gid;
                    int cc = vb + ni * 8 + tig * 2;
                    Cs[rr * 68 + cc]           = acc[mi][ni][0] + sbs[cc];
                    Cs[rr * 68 + cc + 1]       = acc[mi][ni][1] + sbs[cc + 1];
                    Cs[(rr + 8) * 68 + cc]     = acc[mi][ni][2] + sbs[cc];
                    Cs[(rr + 8) * 68 + cc + 1] = acc[mi][ni][3] + sbs[cc + 1];
                }
        }
        __syncthreads();
#pragma unroll
        for (int it = 0; it < 4; it++) {
            int idx = tid + 256 * it;
            int row = idx >> 4, c4 = (idx & 15) * 4;
            *(float4*)&g_mixpre[(size_t)(b * LL + l0 + p * 64 + row) * DD + m * 64 + c4] =
                *(float4*)&Cs[row * 68 + c4];
        }
        __syncthreads();
    }
}

// ---------------- LN helpers ----------------
__device__ __forceinline__ float blk_sum128(float v, float* sbuf)
{
#pragma unroll
    for (int o = 16; o; o >>= 1) v += __shfl_xor_sync(0xffffffffu, v, o);
    __syncthreads();
    if ((threadIdx.x & 31) == 0) sbuf[threadIdx.x >> 5] = v;
    __syncthreads();
    return sbuf[0] + sbuf[1] + sbuf[2] + sbuf[3];
}

__global__ void __launch_bounds__(128)
ln_mix_kernel(const float* __restrict__ g1, const float* __restrict__ b1,
              const float* __restrict__ g2, const float* __restrict__ b2)
{
    __shared__ float sbuf[4];
    size_t row = blockIdx.x;
    int t = threadIdx.x;
    const float* r = g_mixpre + row * DD;
    float v[4];
#pragma unroll
    for (int i = 0; i < 4; i++) v[i] = r[t + 128 * i];
    float mean = blk_sum128(v[0] + v[1] + v[2] + v[3], sbuf) * (1.0f / 512.0f);
    float sq = 0.f;
#pragma unroll
    for (int i = 0; i < 4; i++) { float d = v[i] - mean; sq += d * d; }
    float var = blk_sum128(sq, sbuf) * (1.0f / 512.0f);
    float inv = rsqrtf(var + 1e-5f);
    float mx[4];
#pragma unroll
    for (int i = 0; i < 4; i++) {
        int c = t + 128 * i;
        mx[i] = (v[i] - mean) * inv * g1[c] + b1[c];
        g_mix[row * DD + c] = mx[i];
    }
    float mean2 = blk_sum128(mx[0] + mx[1] + mx[2] + mx[3], sbuf) * (1.0f / 512.0f);
    float sq2 = 0.f;
#pragma unroll
    for (int i = 0; i < 4; i++) { float d = mx[i] - mean2; sq2 += d * d; }
    float var2 = blk_sum128(sq2, sbuf) * (1.0f / 512.0f);
    float inv2 = rsqrtf(var2 + 1e-5f);
#pragma unroll
    for (int i = 0; i < 4; i++) {
        int c = t + 128 * i;
        g_u[row * DD + c] = (mx[i] - mean2) * inv2 * g2[c] + b2[c];
    }
}

// ============ bottleneck 1x1 + GLU via tf32 mma — double-buffered ============
// block 128 rows x 64 real cols (128 virtual: even=ga, odd=gb). 8 warps (4m x 2n).
__global__ void __launch_bounds__(256)
bneck_glu_mma(const float* __restrict__ bw, const float* __restrict__ bb)
{
    __shared__ float As[2][16][132];   // [buf][k][row]
    __shared__ float Bs[2][16][132];   // [buf][k][vcol]
    __shared__ float Cs[32][68];
    int tid = threadIdx.x;
    int warp = tid >> 5, lane = tid & 31;
    int mw = warp & 3, nw = warp >> 2;
    int gid = lane >> 2, tig = lane & 3;
    int r0 = blockIdx.y * 128, n0 = blockIdx.x * 64;

    float acc[2][8][4] = {};

    int arow = tid >> 1;            // 0..127
    int akq  = (tid & 1) * 8;       // 0 or 8
    int vcol = tid >> 1;
    int brr  = (vcol & 1) ? (512 + n0 + (vcol >> 1)) : (n0 + (vcol >> 1));

    const float* pA = &g_u[(size_t)(r0 + arow) * 512 + akq];
    const float* pB = &bw[(size_t)brr * 512 + akq];

    float ar[8], br[8];
    *(float4*)&ar[0] = *(const float4*)pA;
    *(float4*)&ar[4] = *(const float4*)(pA + 4);
    *(float4*)&br[0] = *(const float4*)pB;
    *(float4*)&br[4] = *(const float4*)(pB + 4);
#pragma unroll
    for (int j = 0; j < 8; j++) {
        As[0][akq + j][arow] = tf32r(ar[j]);
        Bs[0][akq + j][vcol] = tf32r(br[j]);
    }
    __syncthreads();

    for (int t = 0; t < 32; t++) {
        int cur = t & 1;
        if (t < 31) {
            const float* qA = pA + (t + 1) * 16;
            const float* qB = pB + (t + 1) * 16;
            *(float4*)&ar[0] = *(const float4*)qA;
            *(float4*)&ar[4] = *(const float4*)(qA + 4);
            *(float4*)&br[0] = *(const float4*)qB;
            *(float4*)&br[4] = *(const float4*)(qB + 4);
        }
#pragma unroll
        for (int kk = 0; kk < 16; kk += 8) {
            uint32_t a[2][4];
#pragma unroll
            for (int mi = 0; mi < 2; mi++) {
                int rb = mw * 32 + mi * 16;
                a[mi][0] = __float_as_uint(As[cur][kk + tig][rb + gid]);
                a[mi][1] = __float_as_uint(As[cur][kk + tig][rb + gid + 8]);
                a[mi][2] = __float_as_uint(As[cur][kk + tig + 4][rb + gid]);
                a[mi][3] = __float_as_uint(As[cur][kk + tig + 4][rb + gid + 8]);
            }
            uint32_t bfr[8][2];
#pragma unroll
            for (int ni = 0; ni < 8; ni++) {
                int vb = nw * 64 + ni * 8;
                bfr[ni][0] = __float_as_uint(Bs[cur][kk + tig][vb + gid]);
                bfr[ni][1] = __float_as_uint(Bs[cur][kk + tig + 4][vb + gid]);
            }
#pragma unroll
            for (int mi = 0; mi < 2; mi++)
#pragma unroll
                for (int ni = 0; ni < 8; ni++)
                    mma_tf32(acc[mi][ni], a[mi], bfr[ni]);
        }
        if (t < 31) {
#pragma unroll
            for (int j = 0; j < 8; j++) {
                As[cur ^ 1][akq + j][arow] = tf32r(ar[j]);
                Bs[cur ^ 1][akq + j][vcol] = tf32r(br[j]);
            }
        }
        __syncthreads();
    }

    float bbA[8], bbB[8];
#pragma unroll
    for (int ni = 0; ni < 8; ni++) {
        int cR = n0 + nw * 32 + ni * 4 + tig;
        bbA[ni] = bb[cR];
        bbB[ni] = bb[512 + cR];
    }
    for (int p = 0; p < 4; p++) {
        if (mw == p) {
#pragma unroll
            for (int mi = 0; mi < 2; mi++)
#pragma unroll
                for (int ni = 0; ni < 8; ni++) {
                    int cc = nw * 32 + ni * 4 + tig;
                    float ga0 = acc[mi][ni][0] + bbA[ni];
                    float gb0 = acc[mi][ni][1] + bbB[ni];
                    float ga1 = acc[mi][ni][2] + bbA[ni];
                    float gb1 = acc[mi][ni][3] + bbB[ni];
                    Cs[mi * 16 + gid][cc]     = ga0 * sigmoidf_(gb0);
                    Cs[mi * 16 + gid + 8][cc] = ga1 * sigmoidf_(gb1);
                }
        }
        __syncthreads();
        {
            int row = tid >> 3, c = (tid & 7) * 8;
            float4 v0 = *(float4*)&Cs[row][c];
            float4 v1 = *(float4*)&Cs[row][c + 4];
            float* op = &g_c0[(size_t)(r0 + p * 32 + row) * 512 + n0 + c];
            *(float4*)op = v0;
            *(float4*)(op + 4) = v1;
        }
        __syncthreads();
    }
}

// ============ depthwise conv (K=31, pad 15) — register sliding window ============
__global__ void __launch_bounds__(256)
dwconv_kernel(const float* __restrict__ dw, const float* __restrict__ dwb)
{
    __shared__ float ins[158 * 64];
    __shared__ float wts[64 * 31];
    __shared__ float bs[64];
    int tid = threadIdx.x;
    int c0 = blockIdx.x * 64;
    int l0 = blockIdx.y * 128;
    int b  = blockIdx.z;
    for (int i = tid; i < 158 * 64; i += 256) {
        int rr = i >> 6, c = i & 63;
        int l = l0 - 15 + rr;
        ins[i] = (l >= 0 && l < LL) ? g_c0[((size_t)(b * LL + l)) * DD + c0 + c] : 0.f;
    }
    for (int i = tid; i < 64 * 31; i += 256)
        wts[i] = dw[c0 * 31 + i];
    if (tid < 64) bs[tid] = dwb[c0 + tid];
    __syncthreads();
    int tx = tid & 63, ty = tid >> 6;
    float w[31];
#pragma unroll
    for (int j = 0; j < 31; j++) w[j] = wts[tx * 31 + j];
    float bias = bs[tx];
    int base = ty * 32;
    float win[31];
#pragma unroll
    for (int j = 0; j < 30; j++) win[j] = ins[(base + j) * 64 + tx];
#pragma unroll
    for (int li = 0; li < 32; li++) {
        win[30] = ins[(base + li + 30) * 64 + tx];
        float acc = bias;
#pragma unroll
        for (int j = 0; j < 31; j++) acc += win[j] * w[j];
        g_v[((size_t)(b * LL + l0 + base + li)) * DD + c0 + tx] = acc;
#pragma unroll
        for (int j = 0; j < 30; j++) win[j] = win[j + 1];
    }
}

// ============ LN2 + gelu ============
__global__ void __launch_bounds__(128)
ln2_gelu_kernel(const float* __restrict__ g2, const float* __restrict__ b2)
{
    __shared__ float sbuf[4];
    size_t row = blockIdx.x;
    int t = threadIdx.x;
    const float* r = g_v + row * DD;
    float v[4];
#pragma unroll
    for (int i = 0; i < 4; i++) v[i] = r[t + 128 * i];
    float mean = blk_sum128(v[0] + v[1] + v[2] + v[3], sbuf) * (1.0f / 512.0f);
    float sq = 0.f;
#pragma unroll
    for (int i = 0; i < 4; i++) { float d = v[i] - mean; sq += d * d; }
    float var = blk_sum128(sq, sbuf) * (1.0f / 512.0f);
    float inv = rsqrtf(var + 1e-5f);
#pragma unroll
    for (int i = 0; i < 4; i++) {
        int c = t + 128 * i;
        g_w[row * DD + c] = geluf((v[i] - mean) * inv * g2[c] + b2[c]);
    }
}

// ============ final linear + bias + residual via tf32 mma — double-buffered ============
// block 128 rows x 128 cols. 8 warps (4m x 2n). dynamic smem.
__global__ void __launch_bounds__(256)
linear_res_mma(const float* __restrict__ lw, const float* __restrict__ lb,
               float* __restrict__ out)
{
    extern __shared__ float smd[];
    float* Asd = smd;                 // [2][16][132]
    float* Bsd = smd + 4224;          // [2][16][132]
    float* Csd = smd + 8448;          // [32][132]
#define LAS(bf, k, r) Asd[(bf) * 2112 + (k) * 132 + (r)]
#define LBS(bf, k, r) Bsd[(bf) * 2112 + (k) * 132 + (r)]
    int tid = threadIdx.x;
    int warp = tid >> 5, lane = tid & 31;
    int mw = warp & 3, nw = warp >> 2;
    int gid = lane >> 2, tig = lane & 3;
    int r0 = blockIdx.y * 128, n0 = blockIdx.x * 128;

    float acc[2][8][4] = {};

    int arow = tid >> 1;
    int akq  = (tid & 1) * 8;

    const float* pA = &g_w[(size_t)(r0 + arow) * 512 + akq];
    const float* pB = &lw[(size_t)(n0 + arow) * 512 + akq];

    float ar[8], br[8];
    *(float4*)&ar[0] = *(const float4*)pA;
    *(float4*)&ar[4] = *(const float4*)(pA + 4);
    *(float4*)&br[0] = *(const float4*)pB;
    *(float4*)&br[4] = *(const float4*)(pB + 4);
#pragma unroll
    for (int j = 0; j < 8; j++) {
        LAS(0, akq + j, arow) = tf32r(ar[j]);
        LBS(0, akq + j, arow) = tf32r(br[j]);
    }
    __syncthreads();

    for (int t = 0; t < 32; t++) {
        int cur = t & 1;
        if (t < 31) {
            const float* qA = pA + (t + 1) * 16;
            const float* qB = pB + (t + 1) * 16;
            *(float4*)&ar[0] = *(const float4*)qA;
            *(float4*)&ar[4] = *(const float4*)(qA + 4);
            *(float4*)&br[0] = *(const float4*)qB;
            *(float4*)&br[4] = *(const float4*)(qB + 4);
        }
#pragma unroll
        for (int kk = 0; kk < 16; kk += 8) {
            uint32_t a[2][4];
#pragma unroll
            for (int mi = 0; mi < 2; mi++) {
                int rb = mw * 32 + mi * 16;
                a[mi][0] = __float_as_uint(LAS(cur, kk + tig, rb + gid));
                a[mi][1] = __float_as_uint(LAS(cur, kk + tig, rb + gid + 8));
                a[mi][2] = __float_as_uint(LAS(cur, kk + tig + 4, rb + gid));
                a[mi][3] = __float_as_uint(LAS(cur, kk + tig + 4, rb + gid + 8));
            }
            uint32_t bfr[8][2];
#pragma unroll
            for (int ni = 0; ni < 8; ni++) {
                int vb = nw * 64 + ni * 8;
                bfr[ni][0] = __float_as_uint(LBS(cur, kk + tig, vb + gid));
                bfr[ni][1] = __float_as_uint(LBS(cur, kk + tig + 4, vb + gid));
            }
#pragma unroll
            for (int mi = 0; mi < 2; mi++)
#pragma unroll
                for (int ni = 0; ni < 8; ni++)
                    mma_tf32(acc[mi][ni], a[mi], bfr[ni]);
        }
        if (t < 31) {
#pragma unroll
            for (int j = 0; j < 8; j++) {
                LAS(cur ^ 1, akq + j, arow) = tf32r(ar[j]);
                LBS(cur ^ 1, akq + j, arow) = tf32r(br[j]);
            }
        }
        __syncthreads();
    }

    for (int p = 0; p < 4; p++) {
        if (mw == p) {
#pragma unroll
            for (int mi = 0; mi < 2; mi++)
#pragma unroll
                for (int ni = 0; ni < 8; ni++) {
                    int cc = nw * 64 + ni * 8 + tig * 2;
                    Csd[(mi * 16 + gid) * 132 + cc]         = acc[mi][ni][0];
                    Csd[(mi * 16 + gid) * 132 + cc + 1]     = acc[mi][ni][1];
                    Csd[(mi * 16 + gid + 8) * 132 + cc]     = acc[mi][ni][2];
                    Csd[(mi * 16 + gid + 8) * 132 + cc + 1] = acc[mi][ni][3];
                }
        }
        __syncthreads();
        {
            int row = tid >> 3, c0c = (tid & 7) * 16;
            size_t gro = (size_t)(r0 + p * 32 + row) * 512 + n0;
#pragma unroll
            for (int q = 0; q < 4; q++) {
                int c = c0c + q * 4;
                float4 v = *(float4*)&Csd[row * 132 + c];
                float4 mres = *(const float4*)&g_mix[gro + c];
                float4 bl = *(const float4*)&lb[n0 + c];
                v.x += bl.x + mres.x; v.y += bl.y + mres.y;
                v.z += bl.z + mres.z; v.w += bl.w + mres.w;
                *(float4*)&out[gro + c] = v;
            }
        }
        __syncthreads();
    }
#undef LAS
#undef LBS
}

// ---------------- launch ----------------
extern "C" void kernel_launch(void* const* d_in, const int* in_sizes, int n_in,
                              void* d_out, int out_size)
{
    (void)in_sizes; (void)n_in; (void)out_size;
    const float* x      = (const float*)d_in[0];
    const float* w1f1w  = (const float*)d_in[1];
    const float* w1f1b  = (const float*)d_in[2];
    const float* w1f2w  = (const float*)d_in[3];
    const float* w1f2b  = (const float*)d_in[4];
    const float* w2f1w  = (const float*)d_in[5];
    const float* w2f1b  = (const float*)d_in[6];
    const float* w2f2w  = (const float*)d_in[7];
    const float* w2f2b  = (const float*)d_in[8];
    const float* lnmg   = (const float*)d_in[9];
    const float* lnmb   = (const float*)d_in[10];
    const float* c1g    = (const float*)d_in[11];
    const float* c1b    = (const float*)d_in[12];
    const float* bw     = (const float*)d_in[13];
    const float* bb     = (const float*)d_in[14];
    const float* dww    = (const float*)d_in[15];
    const float* dwb    = (const float*)d_in[16];
    const float* c2g    = (const float*)d_in[17];
    const float* c2b    = (const float*)d_in[18];
    const float* lw     = (const float*)d_in[19];
    const float* lb     = (const float*)d_in[20];
    float* out = (float*)d_out;

    const int SGEN_SMEM = (4 * 4160 + 256 + 64 + 64 + 64) * 4;
    const int FC1_SMEM  = (128 * 68 + 64 * 68 * 3 + 128) * 4;
    const int MIX_SMEM  = (128 * 68 + 64 * 68 * 2 + 64) * 4;
    const int LIN_SMEM  = (2 * 2112 * 2 + 32 * 132) * 4;   // 50,688 B
    cudaFuncSetAttribute(sgen_kernel, cudaFuncAttributeMaxDynamicSharedMemorySize, SGEN_SMEM);
    cudaFuncSetAttribute(fc1_mma, cudaFuncAttributeMaxDynamicSharedMemorySize, FC1_SMEM);
    cudaFuncSetAttribute(mixpre_mma, cudaFuncAttributeMaxDynamicSharedMemorySize, MIX_SMEM);
    cudaFuncSetAttribute(linear_res_mma, cudaFuncAttributeMaxDynamicSharedMemorySize, LIN_SMEM);

    fc1_mma<<<dim3(16, 64), 256, FC1_SMEM>>>(x, w1f1w, w1f1b, w2f1w, w2f1b);
    t1_mma<<<dim3(4, 64), 256>>>(x);
    sgen_kernel<<<64, 256, SGEN_SMEM>>>(x, w1f2w, w1f2b, w2f2w, w2f2b);
    mixpre_mma<<<dim3(16, 64), 256, MIX_SMEM>>>();
    ln_mix_kernel<<<BB * LL, 128>>>(lnmg, lnmb, c1g, c1b);
    bneck_glu_mma<<<dim3(8, 128), 256>>>(bw, bb);
    dwconv_kernel<<<dim3(8, 16, 8), 256>>>(dww, dwb);
    ln2_gelu_kernel<<<BB * LL, 128>>>(c2g, c2b);
    linear_res_mma<<<dim3(4, 128), 256, LIN_SMEM>>>(lw, lb, out);
}